// round 6
// baseline (speedup 1.0000x reference)
#include <cuda_runtime.h>
#include <cstdint>

#define BATCH   4
#define HEADS   16
#define SEQ     2048
#define DMODEL  1024
#define HDIM    64
#define TOK     (BATCH*SEQ)       // 8192
// softmax in exp2 domain: scale = (1/sqrt(64)) * log2(e)
#define SCALE2  0.18033688011112042f

#define QB      128               // query rows per fused block
#define TC      64                // key tile

// -------- scratch (allocation-free rule: __device__ globals) --------
__device__ float g_Q[BATCH*HEADS*SEQ*HDIM];   // [b][h][l][dh]
__device__ float g_K[BATCH*HEADS*SEQ*HDIM];
__device__ float g_V[BATCH*HEADS*SEQ*HDIM];
__device__ float g_O[TOK*DMODEL];             // [b*l][h*64+dh]

__device__ __forceinline__ float to_tf32(float x) {
    float r;
    asm("cvt.rna.tf32.f32 %0, %1;" : "=f"(r) : "f"(x));
    return r;
}

__device__ __forceinline__ float ex2(float x) {
    float r;
    asm("ex2.approx.f32 %0, %1;" : "=f"(r) : "f"(x));
    return r;
}

__device__ __forceinline__ void mma_tf32(float c[4],
    uint32_t a0, uint32_t a1, uint32_t a2, uint32_t a3,
    uint32_t b0, uint32_t b1)
{
    asm volatile(
        "mma.sync.aligned.m16n8k8.row.col.f32.tf32.tf32.f32 "
        "{%0,%1,%2,%3}, {%4,%5,%6,%7}, {%8,%9}, {%0,%1,%2,%3};\n"
        : "+f"(c[0]), "+f"(c[1]), "+f"(c[2]), "+f"(c[3])
        : "r"(a0), "r"(a1), "r"(a2), "r"(a3), "r"(b0), "r"(b1));
}

#define NEG_INF __int_as_float(0xff800000)

// ============================================================================
// Projection / output GEMM (TF32 mma). EPI 0: +bias, row-major out.
// EPI 1: +bias, scatter to [b][h][l][dh].   2 CTAs/SM.
// ============================================================================
template<int BM, int BN, int BK, int WM, int WN, int EPI>
__global__ void __launch_bounds__(256, 2)
gemm_mma(const float* __restrict__ Ag, const float* __restrict__ Bg,
         const float* __restrict__ bias, float* __restrict__ out,
         int K, int lda, int ldb)
{
    constexpr int WARPS_M = BM / WM;
    constexpr int MT = WM / 16;
    constexpr int NT = WN / 8;
    constexpr int PAD = 4;

    __shared__ float As[BM][BK + PAD];
    __shared__ float Bs[BK][BN + PAD];

    const int tid  = threadIdx.x;
    const int warp = tid >> 5;
    const int lane = tid & 31;
    const int wm   = warp % WARPS_M;
    const int wn   = warp / WARPS_M;
    const int g    = lane >> 2;
    const int t4   = lane & 3;

    const int bn = blockIdx.x * BN;
    const int bm = blockIdx.y * BM;

    float acc[MT][NT][4];
    #pragma unroll
    for (int mi = 0; mi < MT; ++mi)
        #pragma unroll
        for (int ni = 0; ni < NT; ++ni)
            #pragma unroll
            for (int e = 0; e < 4; ++e) acc[mi][ni][e] = 0.f;

    for (int k0 = 0; k0 < K; k0 += BK) {
        constexpr int AV = BM * BK / 4;
        #pragma unroll
        for (int i = 0; i < AV / 256; ++i) {
            int v = i * 256 + tid;
            int row = v / (BK / 4);
            int kc  = (v % (BK / 4)) * 4;
            float4 x = *(const float4*)(Ag + (size_t)(bm + row) * lda + k0 + kc);
            x.x = to_tf32(x.x); x.y = to_tf32(x.y);
            x.z = to_tf32(x.z); x.w = to_tf32(x.w);
            *(float4*)(&As[row][kc]) = x;
        }
        constexpr int BV = BK * BN / 4;
        #pragma unroll
        for (int i = 0; i < BV / 256; ++i) {
            int v = i * 256 + tid;
            int row = v / (BN / 4);
            int col = (v % (BN / 4)) * 4;
            float4 x = *(const float4*)(Bg + (size_t)(k0 + row) * ldb + bn + col);
            x.x = to_tf32(x.x); x.y = to_tf32(x.y);
            x.z = to_tf32(x.z); x.w = to_tf32(x.w);
            *(float4*)(&Bs[row][col]) = x;
        }
        __syncthreads();

        #pragma unroll
        for (int kk = 0; kk < BK; kk += 8) {
            uint32_t af[MT][4];
            uint32_t bf[NT][2];
            #pragma unroll
            for (int mi = 0; mi < MT; ++mi) {
                int r = wm * WM + mi * 16;
                af[mi][0] = __float_as_uint(As[r + g    ][kk + t4    ]);
                af[mi][1] = __float_as_uint(As[r + g + 8][kk + t4    ]);
                af[mi][2] = __float_as_uint(As[r + g    ][kk + t4 + 4]);
                af[mi][3] = __float_as_uint(As[r + g + 8][kk + t4 + 4]);
            }
            #pragma unroll
            for (int ni = 0; ni < NT; ++ni) {
                int c = wn * WN + ni * 8 + g;
                bf[ni][0] = __float_as_uint(Bs[kk + t4    ][c]);
                bf[ni][1] = __float_as_uint(Bs[kk + t4 + 4][c]);
            }
            #pragma unroll
            for (int mi = 0; mi < MT; ++mi)
                #pragma unroll
                for (int ni = 0; ni < NT; ++ni)
                    mma_tf32(acc[mi][ni], af[mi][0], af[mi][1], af[mi][2], af[mi][3],
                             bf[ni][0], bf[ni][1]);
        }
        __syncthreads();
    }

    #pragma unroll
    for (int mi = 0; mi < MT; ++mi) {
        #pragma unroll
        for (int ni = 0; ni < NT; ++ni) {
            #pragma unroll
            for (int e = 0; e < 4; ++e) {
                int row = bm + wm * WM + mi * 16 + g + ((e >= 2) ? 8 : 0);
                int col = bn + wn * WN + ni * 8 + t4 * 2 + (e & 1);
                float v = acc[mi][ni][e] + bias[col];
                if (EPI == 0) {
                    out[(size_t)row * DMODEL + col] = v;
                } else {
                    int b  = row >> 11;
                    int l  = row & (SEQ - 1);
                    int h  = col >> 6;
                    int dh = col & (HDIM - 1);
                    out[(((size_t)(b * HEADS + h)) * SEQ + l) * HDIM + dh] = v;
                }
            }
        }
    }
}

// ============================================================================
// Fused attention v3: pass 1 = QK^T + online stats + RAW logit store to attn;
// pass 2 = read raw logits back (no K, no QK recompute), normalize, write
// final P, PV via shuffle-built A-fragments. 2 CTAs/SM.
// smem floats: Ks[64][68] @0 | Vs[64][72] @4352 | Mf @8960 | total 11008
// Qs[128][68] overlays Ks+Vs during init only.
// ============================================================================
#define KS_OFF   0
#define VS_OFF   4352
#define MASK_OFF 8960
#define SMEM_FLOATS 11008
#define SMEM_BYTES  (SMEM_FLOATS*4)

__global__ void __launch_bounds__(256, 2)
fused_attn(const float* __restrict__ gQ, const float* __restrict__ gK,
           const float* __restrict__ gV, const int* __restrict__ mask,
           float* __restrict__ attnOut, float* __restrict__ gO)
{
    extern __shared__ float sm[];
    float* Ks = sm + KS_OFF;
    float* Vs = sm + VS_OFF;
    float* Qs = sm;               // overlay, dead after aq extraction
    float* Mf = sm + MASK_OFF;

    const int tid  = threadIdx.x;
    const int lane = tid & 31;
    const int warp = tid >> 5;
    const int g    = lane >> 2;
    const int t4   = lane & 3;
    const int wrow = warp * 16;

    const int qb = blockIdx.x * QB;
    const int bh = blockIdx.y;
    const int zb = bh >> 4;
    const int zh = bh & 15;

    const float* Q = gQ + ((size_t)bh * SEQ + qb) * HDIM;
    const float* K = gK + (size_t)bh * SEQ * HDIM;
    const float* V = gV + (size_t)bh * SEQ * HDIM;
    float* attn = attnOut + ((size_t)(zh * BATCH + zb) * SEQ + qb) * SEQ;

    // mask -> additive float
    #pragma unroll
    for (int i = 0; i < SEQ / 256; ++i) {
        int c = i * 256 + tid;
        Mf[c] = mask[zb * SEQ + c] ? NEG_INF : 0.f;
    }
    // Q tile -> smem (tf32), then extract persistent A-fragments
    #pragma unroll
    for (int i = 0; i < 8; ++i) {
        int idx = i * 256 + tid;
        int r = idx >> 4, c4 = (idx & 15) << 2;
        float4 x = *(const float4*)(Q + (size_t)r * HDIM + c4);
        x.x = to_tf32(x.x); x.y = to_tf32(x.y);
        x.z = to_tf32(x.z); x.w = to_tf32(x.w);
        *(float4*)(Qs + r * 68 + c4) = x;
    }
    __syncthreads();

    uint32_t aq[8][4];
    #pragma unroll
    for (int kk8 = 0; kk8 < 8; ++kk8) {
        int kk = kk8 * 8;
        aq[kk8][0] = __float_as_uint(Qs[(wrow + g    ) * 68 + kk + t4    ]);
        aq[kk8][1] = __float_as_uint(Qs[(wrow + g + 8) * 68 + kk + t4    ]);
        aq[kk8][2] = __float_as_uint(Qs[(wrow + g    ) * 68 + kk + t4 + 4]);
        aq[kk8][3] = __float_as_uint(Qs[(wrow + g + 8) * 68 + kk + t4 + 4]);
    }

    // ------- pass 1: QK^T, online (m,l), raw logit store -------
    float m0 = NEG_INF, m1 = NEG_INF, l0 = 0.f, l1 = 0.f;

    for (int t = 0; t < SEQ / TC; ++t) {
        __syncthreads();
        const float* Kt = K + (size_t)t * TC * HDIM;
        #pragma unroll
        for (int i = 0; i < 4; ++i) {
            int idx = i * 256 + tid;
            int r = idx >> 4, c4 = (idx & 15) << 2;
            float4 x = *(const float4*)(Kt + (size_t)r * HDIM + c4);
            x.x = to_tf32(x.x); x.y = to_tf32(x.y);
            x.z = to_tf32(x.z); x.w = to_tf32(x.w);
            *(float4*)(Ks + r * 68 + c4) = x;
        }
        __syncthreads();

        float sacc[8][4];
        #pragma unroll
        for (int nt = 0; nt < 8; ++nt)
            #pragma unroll
            for (int e = 0; e < 4; ++e) sacc[nt][e] = 0.f;

        #pragma unroll
        for (int kk8 = 0; kk8 < 8; ++kk8) {
            int kk = kk8 * 8;
            #pragma unroll
            for (int nt = 0; nt < 8; ++nt) {
                uint32_t b0 = __float_as_uint(Ks[(nt * 8 + g) * 68 + kk + t4    ]);
                uint32_t b1 = __float_as_uint(Ks[(nt * 8 + g) * 68 + kk + t4 + 4]);
                mma_tf32(sacc[nt], aq[kk8][0], aq[kk8][1], aq[kk8][2], aq[kk8][3], b0, b1);
            }
        }

        float tm0 = NEG_INF, tm1 = NEG_INF;
        #pragma unroll
        for (int nt = 0; nt < 8; ++nt) {
            float mk0 = Mf[t * TC + nt * 8 + t4 * 2];
            float mk1 = Mf[t * TC + nt * 8 + t4 * 2 + 1];
            sacc[nt][0] = sacc[nt][0] * SCALE2 + mk0;
            sacc[nt][1] = sacc[nt][1] * SCALE2 + mk1;
            sacc[nt][2] = sacc[nt][2] * SCALE2 + mk0;
            sacc[nt][3] = sacc[nt][3] * SCALE2 + mk1;
            tm0 = fmaxf(tm0, fmaxf(sacc[nt][0], sacc[nt][1]));
            tm1 = fmaxf(tm1, fmaxf(sacc[nt][2], sacc[nt][3]));
            // raw logit store (overwritten with normalized P in pass 2)
            float* d0 = attn + (size_t)(wrow + g) * SEQ + t * TC + nt * 8 + t4 * 2;
            *(float2*)d0 = make_float2(sacc[nt][0], sacc[nt][1]);
            *(float2*)(d0 + 8 * SEQ) = make_float2(sacc[nt][2], sacc[nt][3]);
        }
        tm0 = fmaxf(tm0, __shfl_xor_sync(0xffffffffu, tm0, 1));
        tm0 = fmaxf(tm0, __shfl_xor_sync(0xffffffffu, tm0, 2));
        tm1 = fmaxf(tm1, __shfl_xor_sync(0xffffffffu, tm1, 1));
        tm1 = fmaxf(tm1, __shfl_xor_sync(0xffffffffu, tm1, 2));

        float mn0 = fmaxf(m0, tm0), mn1 = fmaxf(m1, tm1);
        float ms0 = (mn0 == NEG_INF) ? 0.f : mn0;
        float ms1 = (mn1 == NEG_INF) ? 0.f : mn1;

        float sum0 = 0.f, sum1 = 0.f;
        #pragma unroll
        for (int nt = 0; nt < 8; ++nt) {
            sum0 += ex2(sacc[nt][0] - ms0) + ex2(sacc[nt][1] - ms0);
            sum1 += ex2(sacc[nt][2] - ms1) + ex2(sacc[nt][3] - ms1);
        }
        sum0 += __shfl_xor_sync(0xffffffffu, sum0, 1);
        sum0 += __shfl_xor_sync(0xffffffffu, sum0, 2);
        sum1 += __shfl_xor_sync(0xffffffffu, sum1, 1);
        sum1 += __shfl_xor_sync(0xffffffffu, sum1, 2);

        float a0 = (m0 == NEG_INF) ? 0.f : ex2(m0 - ms0);
        float a1 = (m1 == NEG_INF) ? 0.f : ex2(m1 - ms1);
        l0 = l0 * a0 + sum0;
        l1 = l1 * a1 + sum1;
        m0 = mn0; m1 = mn1;
    }

    const float invl0 = (l0 > 0.f) ? 1.f / l0 : 0.f;
    const float invl1 = (l1 > 0.f) ? 1.f / l1 : 0.f;
    const float mf0 = (m0 == NEG_INF) ? 0.f : m0;
    const float mf1 = (m1 == NEG_INF) ? 0.f : m1;

    // ------- pass 2: reload raw logits, normalize, write P, PV -------
    float oacc[8][4];
    #pragma unroll
    for (int nt = 0; nt < 8; ++nt)
        #pragma unroll
        for (int e = 0; e < 4; ++e) oacc[nt][e] = 0.f;

    const int srcA = (lane & ~3) | (t4 >> 1);   // col t4   source lane
    const int srcB = srcA + 2;                  // col t4+4 source lane
    const bool odd = (t4 & 1);

    for (int t = 0; t < SEQ / TC; ++t) {
        __syncthreads();
        const float* Vt = V + (size_t)t * TC * HDIM;
        #pragma unroll
        for (int i = 0; i < 4; ++i) {
            int idx = i * 256 + tid;
            int r = idx >> 4, c4 = (idx & 15) << 2;
            float4 y = *(const float4*)(Vt + (size_t)r * HDIM + c4);
            y.x = to_tf32(y.x); y.y = to_tf32(y.y);
            y.z = to_tf32(y.z); y.w = to_tf32(y.w);
            *(float4*)(Vs + r * 72 + c4) = y;
        }
        __syncthreads();

        // reload raw logits (each thread reads exactly what it wrote)
        float sacc[8][4];
        #pragma unroll
        for (int nt = 0; nt < 8; ++nt) {
            float* d0 = attn + (size_t)(wrow + g) * SEQ + t * TC + nt * 8 + t4 * 2;
            float2 r0 = *(const float2*)d0;
            float2 r1 = *(const float2*)(d0 + 8 * SEQ);
            sacc[nt][0] = ex2(r0.x - mf0) * invl0;
            sacc[nt][1] = ex2(r0.y - mf0) * invl0;
            sacc[nt][2] = ex2(r1.x - mf1) * invl1;
            sacc[nt][3] = ex2(r1.y - mf1) * invl1;
            *(float2*)d0 = make_float2(sacc[nt][0], sacc[nt][1]);
            *(float2*)(d0 + 8 * SEQ) = make_float2(sacc[nt][2], sacc[nt][3]);
        }

        // PV: A-fragments from sacc via lane shuffles (C->A layout permute)
        #pragma unroll
        for (int kt = 0; kt < 8; ++kt) {
            float x0 = __shfl_sync(0xffffffffu, sacc[kt][0], srcA);
            float x1 = __shfl_sync(0xffffffffu, sacc[kt][1], srcA);
            float y0 = __shfl_sync(0xffffffffu, sacc[kt][0], srcB);
            float y1 = __shfl_sync(0xffffffffu, sacc[kt][1], srcB);
            float z0 = __shfl_sync(0xffffffffu, sacc[kt][2], srcA);
            float z1 = __shfl_sync(0xffffffffu, sacc[kt][3], srcA);
            float w0 = __shfl_sync(0xffffffffu, sacc[kt][2], srcB);
            float w1 = __shfl_sync(0xffffffffu, sacc[kt][3], srcB);
            uint32_t a0 = __float_as_uint(to_tf32(odd ? x1 : x0));
            uint32_t a1 = __float_as_uint(to_tf32(odd ? z1 : z0));
            uint32_t a2 = __float_as_uint(to_tf32(odd ? y1 : y0));
            uint32_t a3 = __float_as_uint(to_tf32(odd ? w1 : w0));
            int kb = kt * 8;
            #pragma unroll
            for (int nt = 0; nt < 8; ++nt) {
                uint32_t b0 = __float_as_uint(Vs[(kb + t4    ) * 72 + nt * 8 + g]);
                uint32_t b1 = __float_as_uint(Vs[(kb + t4 + 4) * 72 + nt * 8 + g]);
                mma_tf32(oacc[nt], a0, a1, a2, a3, b0, b1);
            }
        }
    }

    // write O block to g_O [b*l][h*64+dv]
    #pragma unroll
    for (int nt = 0; nt < 8; ++nt) {
        #pragma unroll
        for (int e = 0; e < 4; ++e) {
            int rl  = wrow + g + ((e >= 2) ? 8 : 0);
            int col = nt * 8 + t4 * 2 + (e & 1);
            gO[((size_t)zb * SEQ + qb + rl) * DMODEL + zh * HDIM + col] = oacc[nt][e];
        }
    }
}

// ============================================================================
extern "C" void kernel_launch(void* const* d_in, const int* in_sizes, int n_in,
                              void* d_out, int out_size)
{
    const float* q    = (const float*)d_in[0];
    const float* k    = (const float*)d_in[1];
    const float* v    = (const float*)d_in[2];
    const int*   mask = (const int*)d_in[3];
    const float* Wq = (const float*)d_in[4];
    const float* bq = (const float*)d_in[5];
    const float* Wk = (const float*)d_in[6];
    const float* bk = (const float*)d_in[7];
    const float* Wv = (const float*)d_in[8];
    const float* bv = (const float*)d_in[9];
    const float* Wo = (const float*)d_in[10];
    const float* bo = (const float*)d_in[11];

    float* out  = (float*)d_out;                         // [4,2048,1024]
    float* attn = out + (size_t)TOK * DMODEL;            // [16,4,2048,2048]

    float *gq, *gk, *gv, *go;
    cudaGetSymbolAddress((void**)&gq, g_Q);
    cudaGetSymbolAddress((void**)&gk, g_K);
    cudaGetSymbolAddress((void**)&gv, g_V);
    cudaGetSymbolAddress((void**)&go, g_O);

    dim3 blk(256);
    dim3 gproj(DMODEL / 128, TOK / 128);

    // Q/K/V projections
    gemm_mma<128,128,32,32,64,1><<<gproj, blk>>>(q, Wq, bq, gq, DMODEL, DMODEL, DMODEL);
    gemm_mma<128,128,32,32,64,1><<<gproj, blk>>>(k, Wk, bk, gk, DMODEL, DMODEL, DMODEL);
    gemm_mma<128,128,32,32,64,1><<<gproj, blk>>>(v, Wv, bv, gv, DMODEL, DMODEL, DMODEL);

    // fused scores + softmax + attn-write + PV
    dim3 gfa(SEQ / QB, BATCH * HEADS);
    fused_attn<<<gfa, blk, SMEM_BYTES>>>(gq, gk, gv, mask, attn, go);

    // output projection
    gemm_mma<128,128,32,32,64,0><<<gproj, blk>>>(go, Wo, bo, out, DMODEL, DMODEL, DMODEL);
}

// round 7
// speedup vs baseline: 1.1130x; 1.1130x over previous
#include <cuda_runtime.h>
#include <cstdint>

#define BATCH   4
#define HEADS   16
#define SEQ     2048
#define DMODEL  1024
#define HDIM    64
#define TOK     (BATCH*SEQ)       // 8192
// softmax in exp2 domain: scale = (1/sqrt(64)) * log2(e)
#define SCALE2  0.18033688011112042f

#define QB      128               // query rows per fused block
#define TC      64                // key tile

// -------- scratch (allocation-free rule: __device__ globals) --------
__device__ float g_Q[BATCH*HEADS*SEQ*HDIM];   // [b][h][l][dh]
__device__ float g_K[BATCH*HEADS*SEQ*HDIM];
__device__ float g_V[BATCH*HEADS*SEQ*HDIM];
__device__ float g_O[TOK*DMODEL];             // [b*l][h*64+dh]

__device__ __forceinline__ float to_tf32(float x) {
    float r;
    asm("cvt.rna.tf32.f32 %0, %1;" : "=f"(r) : "f"(x));
    return r;
}

__device__ __forceinline__ float ex2(float x) {
    float r;
    asm("ex2.approx.f32 %0, %1;" : "=f"(r) : "f"(x));
    return r;
}

__device__ __forceinline__ void mma_tf32(float c[4],
    uint32_t a0, uint32_t a1, uint32_t a2, uint32_t a3,
    uint32_t b0, uint32_t b1)
{
    asm volatile(
        "mma.sync.aligned.m16n8k8.row.col.f32.tf32.tf32.f32 "
        "{%0,%1,%2,%3}, {%4,%5,%6,%7}, {%8,%9}, {%0,%1,%2,%3};\n"
        : "+f"(c[0]), "+f"(c[1]), "+f"(c[2]), "+f"(c[3])
        : "r"(a0), "r"(a1), "r"(a2), "r"(a3), "r"(b0), "r"(b1));
}

#define NEG_INF __int_as_float(0xff800000)

// ============================================================================
// Software-pipelined projection GEMM (double-buffered smem, 1 sync/iter).
// C[8192x1024] = A @ W + bias.  EPI 0: row-major out. EPI 1: head scatter.
// grid.z selects (A, W, bias, out) triple for merged QKV launch.
// Warp layout: 4 warps M x 2 warps N, warp tile 32x64, BK=32.
// Dynamic smem: As[2][128][36] @0 | Bs[2][32][132] @9216 floats; 70656 B.
// ============================================================================
#define PJ_AS(buf)  (smf + (buf) * 4608)
#define PJ_BS(buf)  (smf + 9216 + (buf) * 4224)
#define PJ_SMEM_BYTES 70656

template<int EPI>
__global__ void __launch_bounds__(256, 2)
proj_gemm(const float* __restrict__ A0, const float* __restrict__ A1,
          const float* __restrict__ A2,
          const float* __restrict__ W0, const float* __restrict__ W1,
          const float* __restrict__ W2,
          const float* __restrict__ b0, const float* __restrict__ b1,
          const float* __restrict__ b2,
          float* __restrict__ o0, float* __restrict__ o1, float* __restrict__ o2)
{
    extern __shared__ float smf[];

    const int z = blockIdx.z;
    const float* Ag   = (z == 0) ? A0 : (z == 1) ? A1 : A2;
    const float* Wg   = (z == 0) ? W0 : (z == 1) ? W1 : W2;
    const float* bias = (z == 0) ? b0 : (z == 1) ? b1 : b2;
    float* out        = (z == 0) ? o0 : (z == 1) ? o1 : o2;

    const int tid  = threadIdx.x;
    const int warp = tid >> 5;
    const int lane = tid & 31;
    const int wm   = warp & 3;          // 0..3 (M)
    const int wn   = warp >> 2;         // 0..1 (N)
    const int g    = lane >> 2;
    const int t4   = lane & 3;

    const int bn = blockIdx.x * 128;
    const int bm = blockIdx.y * 128;

    // per-thread load coords
    const int arow = tid >> 1;                 // A: 128 rows, 2 threads/row
    const int acol = (tid & 1) * 16;           // two float4 slots per j-step? no:
    // A tile: 128x32 floats = 1024 float4; thread does 4: lin = j*256+tid
    // B tile: 32x128 floats = 1024 float4 likewise.
    (void)arow; (void)acol;

    float acc[2][8][4];
    #pragma unroll
    for (int mi = 0; mi < 2; ++mi)
        #pragma unroll
        for (int ni = 0; ni < 8; ++ni)
            #pragma unroll
            for (int e = 0; e < 4; ++e) acc[mi][ni][e] = 0.f;

    // ---- prologue: stage tile 0 ----
    {
        float* As = PJ_AS(0);
        float* Bs = PJ_BS(0);
        #pragma unroll
        for (int j = 0; j < 4; ++j) {
            int lin = j * 256 + tid;
            int row = lin >> 3, c4 = (lin & 7) * 4;
            float4 x = *(const float4*)(Ag + (size_t)(bm + row) * DMODEL + c4);
            x.x = to_tf32(x.x); x.y = to_tf32(x.y);
            x.z = to_tf32(x.z); x.w = to_tf32(x.w);
            *(float4*)(As + row * 36 + c4) = x;
        }
        #pragma unroll
        for (int j = 0; j < 4; ++j) {
            int lin = j * 256 + tid;
            int row = lin >> 5, c4 = (lin & 31) * 4;
            float4 x = *(const float4*)(Wg + (size_t)row * DMODEL + bn + c4);
            x.x = to_tf32(x.x); x.y = to_tf32(x.y);
            x.z = to_tf32(x.z); x.w = to_tf32(x.w);
            *(float4*)(Bs + row * 132 + c4) = x;
        }
    }
    __syncthreads();

    for (int t = 0; t < 32; ++t) {
        const int cur = t & 1, nxt = cur ^ 1;
        float* Ac = PJ_AS(cur);
        float* Bc = PJ_BS(cur);
        float* An = PJ_AS(nxt);
        float* Bn = PJ_BS(nxt);
        const int kt = (t < 31) ? (t + 1) : 31;   // clamp; last prefetch unused
        const int kg = kt * 32;

        // ---- prefetch A(t+1) into regs ----
        float4 ra[4];
        #pragma unroll
        for (int j = 0; j < 4; ++j) {
            int lin = j * 256 + tid;
            int row = lin >> 3, c4 = (lin & 7) * 4;
            ra[j] = *(const float4*)(Ag + (size_t)(bm + row) * DMODEL + kg + c4);
        }

        // ---- compute kk = 0, 8 ----
        #pragma unroll
        for (int kh = 0; kh < 2; ++kh) {
            const int kk = kh * 8;
            uint32_t af[2][4];
            uint32_t bf[8][2];
            #pragma unroll
            for (int mi = 0; mi < 2; ++mi) {
                int r = wm * 32 + mi * 16;
                af[mi][0] = __float_as_uint(Ac[(r + g    ) * 36 + kk + t4    ]);
                af[mi][1] = __float_as_uint(Ac[(r + g + 8) * 36 + kk + t4    ]);
                af[mi][2] = __float_as_uint(Ac[(r + g    ) * 36 + kk + t4 + 4]);
                af[mi][3] = __float_as_uint(Ac[(r + g + 8) * 36 + kk + t4 + 4]);
            }
            #pragma unroll
            for (int ni = 0; ni < 8; ++ni) {
                int c = wn * 64 + ni * 8 + g;
                bf[ni][0] = __float_as_uint(Bc[(kk + t4    ) * 132 + c]);
                bf[ni][1] = __float_as_uint(Bc[(kk + t4 + 4) * 132 + c]);
            }
            #pragma unroll
            for (int mi = 0; mi < 2; ++mi)
                #pragma unroll
                for (int ni = 0; ni < 8; ++ni)
                    mma_tf32(acc[mi][ni], af[mi][0], af[mi][1], af[mi][2], af[mi][3],
                             bf[ni][0], bf[ni][1]);
        }

        // ---- store A(t+1) ----
        #pragma unroll
        for (int j = 0; j < 4; ++j) {
            int lin = j * 256 + tid;
            int row = lin >> 3, c4 = (lin & 7) * 4;
            float4 x = ra[j];
            x.x = to_tf32(x.x); x.y = to_tf32(x.y);
            x.z = to_tf32(x.z); x.w = to_tf32(x.w);
            *(float4*)(An + row * 36 + c4) = x;
        }

        // ---- prefetch B(t+1) into regs ----
        float4 rb[4];
        #pragma unroll
        for (int j = 0; j < 4; ++j) {
            int lin = j * 256 + tid;
            int row = lin >> 5, c4 = (lin & 31) * 4;
            rb[j] = *(const float4*)(Wg + (size_t)(kg + row) * DMODEL + bn + c4);
        }

        // ---- compute kk = 16, 24 ----
        #pragma unroll
        for (int kh = 0; kh < 2; ++kh) {
            const int kk = 16 + kh * 8;
            uint32_t af[2][4];
            uint32_t bf[8][2];
            #pragma unroll
            for (int mi = 0; mi < 2; ++mi) {
                int r = wm * 32 + mi * 16;
                af[mi][0] = __float_as_uint(Ac[(r + g    ) * 36 + kk + t4    ]);
                af[mi][1] = __float_as_uint(Ac[(r + g + 8) * 36 + kk + t4    ]);
                af[mi][2] = __float_as_uint(Ac[(r + g    ) * 36 + kk + t4 + 4]);
                af[mi][3] = __float_as_uint(Ac[(r + g + 8) * 36 + kk + t4 + 4]);
            }
            #pragma unroll
            for (int ni = 0; ni < 8; ++ni) {
                int c = wn * 64 + ni * 8 + g;
                bf[ni][0] = __float_as_uint(Bc[(kk + t4    ) * 132 + c]);
                bf[ni][1] = __float_as_uint(Bc[(kk + t4 + 4) * 132 + c]);
            }
            #pragma unroll
            for (int mi = 0; mi < 2; ++mi)
                #pragma unroll
                for (int ni = 0; ni < 8; ++ni)
                    mma_tf32(acc[mi][ni], af[mi][0], af[mi][1], af[mi][2], af[mi][3],
                             bf[ni][0], bf[ni][1]);
        }

        // ---- store B(t+1) ----
        #pragma unroll
        for (int j = 0; j < 4; ++j) {
            int lin = j * 256 + tid;
            int row = lin >> 5, c4 = (lin & 31) * 4;
            float4 x = rb[j];
            x.x = to_tf32(x.x); x.y = to_tf32(x.y);
            x.z = to_tf32(x.z); x.w = to_tf32(x.w);
            *(float4*)(Bn + row * 132 + c4) = x;
        }
        __syncthreads();
    }

    // ---- epilogue ----
    #pragma unroll
    for (int mi = 0; mi < 2; ++mi) {
        #pragma unroll
        for (int ni = 0; ni < 8; ++ni) {
            #pragma unroll
            for (int e = 0; e < 4; ++e) {
                int row = bm + wm * 32 + mi * 16 + g + ((e >= 2) ? 8 : 0);
                int col = bn + wn * 64 + ni * 8 + t4 * 2 + (e & 1);
                float v = acc[mi][ni][e] + bias[col];
                if (EPI == 0) {
                    out[(size_t)row * DMODEL + col] = v;
                } else {
                    int b  = row >> 11;
                    int l  = row & (SEQ - 1);
                    int h  = col >> 6;
                    int dh = col & (HDIM - 1);
                    out[(((size_t)(b * HEADS + h)) * SEQ + l) * HDIM + dh] = v;
                }
            }
        }
    }
}

// ============================================================================
// Fused attention (R5, proven): pass 1 = QK^T + online stats; pass 2 =
// recompute QK^T, normalize, direct attn write, PV via shuffle A-frags.
// 2 CTAs/SM.  smem floats: Ks[64][68] @0 | Vs[64][72] @4352 | Mf @8960.
// ============================================================================
#define KS_OFF   0
#define VS_OFF   4352
#define MASK_OFF 8960
#define SMEM_FLOATS 11008
#define SMEM_BYTES  (SMEM_FLOATS*4)

__global__ void __launch_bounds__(256, 2)
fused_attn(const float* __restrict__ gQ, const float* __restrict__ gK,
           const float* __restrict__ gV, const int* __restrict__ mask,
           float* __restrict__ attnOut, float* __restrict__ gO)
{
    extern __shared__ float sm[];
    float* Ks = sm + KS_OFF;
    float* Vs = sm + VS_OFF;
    float* Qs = sm;               // overlay, dead after aq extraction
    float* Mf = sm + MASK_OFF;

    const int tid  = threadIdx.x;
    const int lane = tid & 31;
    const int warp = tid >> 5;
    const int g    = lane >> 2;
    const int t4   = lane & 3;
    const int wrow = warp * 16;

    const int qb = blockIdx.x * QB;
    const int bh = blockIdx.y;
    const int zb = bh >> 4;
    const int zh = bh & 15;

    const float* Q = gQ + ((size_t)bh * SEQ + qb) * HDIM;
    const float* K = gK + (size_t)bh * SEQ * HDIM;
    const float* V = gV + (size_t)bh * SEQ * HDIM;
    float* attn = attnOut + ((size_t)(zh * BATCH + zb) * SEQ + qb) * SEQ;

    #pragma unroll
    for (int i = 0; i < SEQ / 256; ++i) {
        int c = i * 256 + tid;
        Mf[c] = mask[zb * SEQ + c] ? NEG_INF : 0.f;
    }
    #pragma unroll
    for (int i = 0; i < 8; ++i) {
        int idx = i * 256 + tid;
        int r = idx >> 4, c4 = (idx & 15) << 2;
        float4 x = *(const float4*)(Q + (size_t)r * HDIM + c4);
        x.x = to_tf32(x.x); x.y = to_tf32(x.y);
        x.z = to_tf32(x.z); x.w = to_tf32(x.w);
        *(float4*)(Qs + r * 68 + c4) = x;
    }
    __syncthreads();

    uint32_t aq[8][4];
    #pragma unroll
    for (int kk8 = 0; kk8 < 8; ++kk8) {
        int kk = kk8 * 8;
        aq[kk8][0] = __float_as_uint(Qs[(wrow + g    ) * 68 + kk + t4    ]);
        aq[kk8][1] = __float_as_uint(Qs[(wrow + g + 8) * 68 + kk + t4    ]);
        aq[kk8][2] = __float_as_uint(Qs[(wrow + g    ) * 68 + kk + t4 + 4]);
        aq[kk8][3] = __float_as_uint(Qs[(wrow + g + 8) * 68 + kk + t4 + 4]);
    }

    // ---------------- pass 1: online (m, l) ----------------
    float m0 = NEG_INF, m1 = NEG_INF, l0 = 0.f, l1 = 0.f;

    for (int t = 0; t < SEQ / TC; ++t) {
        __syncthreads();
        const float* Kt = K + (size_t)t * TC * HDIM;
        #pragma unroll
        for (int i = 0; i < 4; ++i) {
            int idx = i * 256 + tid;
            int r = idx >> 4, c4 = (idx & 15) << 2;
            float4 x = *(const float4*)(Kt + (size_t)r * HDIM + c4);
            x.x = to_tf32(x.x); x.y = to_tf32(x.y);
            x.z = to_tf32(x.z); x.w = to_tf32(x.w);
            *(float4*)(Ks + r * 68 + c4) = x;
        }
        __syncthreads();

        float sacc[8][4];
        #pragma unroll
        for (int nt = 0; nt < 8; ++nt)
            #pragma unroll
            for (int e = 0; e < 4; ++e) sacc[nt][e] = 0.f;

        #pragma unroll
        for (int kk8 = 0; kk8 < 8; ++kk8) {
            int kk = kk8 * 8;
            #pragma unroll
            for (int nt = 0; nt < 8; ++nt) {
                uint32_t b0 = __float_as_uint(Ks[(nt * 8 + g) * 68 + kk + t4    ]);
                uint32_t b1 = __float_as_uint(Ks[(nt * 8 + g) * 68 + kk + t4 + 4]);
                mma_tf32(sacc[nt], aq[kk8][0], aq[kk8][1], aq[kk8][2], aq[kk8][3], b0, b1);
            }
        }

        float tm0 = NEG_INF, tm1 = NEG_INF;
        #pragma unroll
        for (int nt = 0; nt < 8; ++nt) {
            float mk0 = Mf[t * TC + nt * 8 + t4 * 2];
            float mk1 = Mf[t * TC + nt * 8 + t4 * 2 + 1];
            sacc[nt][0] = sacc[nt][0] * SCALE2 + mk0;
            sacc[nt][1] = sacc[nt][1] * SCALE2 + mk1;
            sacc[nt][2] = sacc[nt][2] * SCALE2 + mk0;
            sacc[nt][3] = sacc[nt][3] * SCALE2 + mk1;
            tm0 = fmaxf(tm0, fmaxf(sacc[nt][0], sacc[nt][1]));
            tm1 = fmaxf(tm1, fmaxf(sacc[nt][2], sacc[nt][3]));
        }
        tm0 = fmaxf(tm0, __shfl_xor_sync(0xffffffffu, tm0, 1));
        tm0 = fmaxf(tm0, __shfl_xor_sync(0xffffffffu, tm0, 2));
        tm1 = fmaxf(tm1, __shfl_xor_sync(0xffffffffu, tm1, 1));
        tm1 = fmaxf(tm1, __shfl_xor_sync(0xffffffffu, tm1, 2));

        float mn0 = fmaxf(m0, tm0), mn1 = fmaxf(m1, tm1);
        float ms0 = (mn0 == NEG_INF) ? 0.f : mn0;
        float ms1 = (mn1 == NEG_INF) ? 0.f : mn1;

        float sum0 = 0.f, sum1 = 0.f;
        #pragma unroll
        for (int nt = 0; nt < 8; ++nt) {
            sum0 += ex2(sacc[nt][0] - ms0) + ex2(sacc[nt][1] - ms0);
            sum1 += ex2(sacc[nt][2] - ms1) + ex2(sacc[nt][3] - ms1);
        }
        sum0 += __shfl_xor_sync(0xffffffffu, sum0, 1);
        sum0 += __shfl_xor_sync(0xffffffffu, sum0, 2);
        sum1 += __shfl_xor_sync(0xffffffffu, sum1, 1);
        sum1 += __shfl_xor_sync(0xffffffffu, sum1, 2);

        float a0 = (m0 == NEG_INF) ? 0.f : ex2(m0 - ms0);
        float a1 = (m1 == NEG_INF) ? 0.f : ex2(m1 - ms1);
        l0 = l0 * a0 + sum0;
        l1 = l1 * a1 + sum1;
        m0 = mn0; m1 = mn1;
    }

    const float invl0 = (l0 > 0.f) ? 1.f / l0 : 0.f;
    const float invl1 = (l1 > 0.f) ? 1.f / l1 : 0.f;
    const float mf0 = (m0 == NEG_INF) ? 0.f : m0;
    const float mf1 = (m1 == NEG_INF) ? 0.f : m1;

    // ---------------- pass 2: recompute + P write + PV ----------------
    float oacc[8][4];
    #pragma unroll
    for (int nt = 0; nt < 8; ++nt)
        #pragma unroll
        for (int e = 0; e < 4; ++e) oacc[nt][e] = 0.f;

    const int srcA = (lane & ~3) | (t4 >> 1);   // col t4   source lane
    const int srcB = srcA + 2;                  // col t4+4 source lane
    const bool odd = (t4 & 1);

    for (int t = 0; t < SEQ / TC; ++t) {
        __syncthreads();
        const float* Kt = K + (size_t)t * TC * HDIM;
        const float* Vt = V + (size_t)t * TC * HDIM;
        #pragma unroll
        for (int i = 0; i < 4; ++i) {
            int idx = i * 256 + tid;
            int r = idx >> 4, c4 = (idx & 15) << 2;
            float4 x = *(const float4*)(Kt + (size_t)r * HDIM + c4);
            x.x = to_tf32(x.x); x.y = to_tf32(x.y);
            x.z = to_tf32(x.z); x.w = to_tf32(x.w);
            *(float4*)(Ks + r * 68 + c4) = x;
            float4 y = *(const float4*)(Vt + (size_t)r * HDIM + c4);
            y.x = to_tf32(y.x); y.y = to_tf32(y.y);
            y.z = to_tf32(y.z); y.w = to_tf32(y.w);
            *(float4*)(Vs + r * 72 + c4) = y;
        }
        __syncthreads();

        float sacc[8][4];
        #pragma unroll
        for (int nt = 0; nt < 8; ++nt)
            #pragma unroll
            for (int e = 0; e < 4; ++e) sacc[nt][e] = 0.f;

        #pragma unroll
        for (int kk8 = 0; kk8 < 8; ++kk8) {
            int kk = kk8 * 8;
            #pragma unroll
            for (int nt = 0; nt < 8; ++nt) {
                uint32_t b0 = __float_as_uint(Ks[(nt * 8 + g) * 68 + kk + t4    ]);
                uint32_t b1 = __float_as_uint(Ks[(nt * 8 + g) * 68 + kk + t4 + 4]);
                mma_tf32(sacc[nt], aq[kk8][0], aq[kk8][1], aq[kk8][2], aq[kk8][3], b0, b1);
            }
        }

        // normalize in place + direct attn write (float2, sector-aligned)
        #pragma unroll
        for (int nt = 0; nt < 8; ++nt) {
            float mk0 = Mf[t * TC + nt * 8 + t4 * 2];
            float mk1 = Mf[t * TC + nt * 8 + t4 * 2 + 1];
            sacc[nt][0] = ex2(sacc[nt][0] * SCALE2 + mk0 - mf0) * invl0;
            sacc[nt][1] = ex2(sacc[nt][1] * SCALE2 + mk1 - mf0) * invl0;
            sacc[nt][2] = ex2(sacc[nt][2] * SCALE2 + mk0 - mf1) * invl1;
            sacc[nt][3] = ex2(sacc[nt][3] * SCALE2 + mk1 - mf1) * invl1;
            float* d0 = attn + (size_t)(wrow + g) * SEQ + t * TC + nt * 8 + t4 * 2;
            *(float2*)d0 = make_float2(sacc[nt][0], sacc[nt][1]);
            *(float2*)(d0 + 8 * SEQ) = make_float2(sacc[nt][2], sacc[nt][3]);
        }

        // PV: A-fragments from sacc via lane shuffles (C->A layout permute)
        #pragma unroll
        for (int kt = 0; kt < 8; ++kt) {
            float x0 = __shfl_sync(0xffffffffu, sacc[kt][0], srcA);
            float x1 = __shfl_sync(0xffffffffu, sacc[kt][1], srcA);
            float y0 = __shfl_sync(0xffffffffu, sacc[kt][0], srcB);
            float y1 = __shfl_sync(0xffffffffu, sacc[kt][1], srcB);
            float z0 = __shfl_sync(0xffffffffu, sacc[kt][2], srcA);
            float z1 = __shfl_sync(0xffffffffu, sacc[kt][3], srcA);
            float w0 = __shfl_sync(0xffffffffu, sacc[kt][2], srcB);
            float w1 = __shfl_sync(0xffffffffu, sacc[kt][3], srcB);
            uint32_t a0 = __float_as_uint(to_tf32(odd ? x1 : x0));
            uint32_t a1 = __float_as_uint(to_tf32(odd ? z1 : z0));
            uint32_t a2 = __float_as_uint(to_tf32(odd ? y1 : y0));
            uint32_t a3 = __float_as_uint(to_tf32(odd ? w1 : w0));
            int kb = kt * 8;
            #pragma unroll
            for (int nt = 0; nt < 8; ++nt) {
                uint32_t b0 = __float_as_uint(Vs[(kb + t4    ) * 72 + nt * 8 + g]);
                uint32_t b1 = __float_as_uint(Vs[(kb + t4 + 4) * 72 + nt * 8 + g]);
                mma_tf32(oacc[nt], a0, a1, a2, a3, b0, b1);
            }
        }
    }

    // write O block to g_O [b*l][h*64+dv]
    #pragma unroll
    for (int nt = 0; nt < 8; ++nt) {
        #pragma unroll
        for (int e = 0; e < 4; ++e) {
            int rl  = wrow + g + ((e >= 2) ? 8 : 0);
            int col = nt * 8 + t4 * 2 + (e & 1);
            gO[((size_t)zb * SEQ + qb + rl) * DMODEL + zh * HDIM + col] = oacc[nt][e];
        }
    }
}

// ============================================================================
extern "C" void kernel_launch(void* const* d_in, const int* in_sizes, int n_in,
                              void* d_out, int out_size)
{
    const float* q    = (const float*)d_in[0];
    const float* k    = (const float*)d_in[1];
    const float* v    = (const float*)d_in[2];
    const int*   mask = (const int*)d_in[3];
    const float* Wq = (const float*)d_in[4];
    const float* bq = (const float*)d_in[5];
    const float* Wk = (const float*)d_in[6];
    const float* bk = (const float*)d_in[7];
    const float* Wv = (const float*)d_in[8];
    const float* bv = (const float*)d_in[9];
    const float* Wo = (const float*)d_in[10];
    const float* bo = (const float*)d_in[11];

    float* out  = (float*)d_out;                         // [4,2048,1024]
    float* attn = out + (size_t)TOK * DMODEL;            // [16,4,2048,2048]

    float *gq, *gk, *gv, *go;
    cudaGetSymbolAddress((void**)&gq, g_Q);
    cudaGetSymbolAddress((void**)&gk, g_K);
    cudaGetSymbolAddress((void**)&gv, g_V);
    cudaGetSymbolAddress((void**)&go, g_O);

    static int attr_set = 0;
    if (!attr_set) {
        cudaFuncSetAttribute(proj_gemm<0>, cudaFuncAttributeMaxDynamicSharedMemorySize, PJ_SMEM_BYTES);
        cudaFuncSetAttribute(proj_gemm<1>, cudaFuncAttributeMaxDynamicSharedMemorySize, PJ_SMEM_BYTES);
        attr_set = 1;
    }

    dim3 blk(256);

    // merged Q/K/V projections (z selects input/weight/output)
    dim3 gqkv(DMODEL / 128, TOK / 128, 3);
    proj_gemm<1><<<gqkv, blk, PJ_SMEM_BYTES>>>(q, k, v, Wq, Wk, Wv, bq, bk, bv, gq, gk, gv);

    // fused scores + softmax + attn-write + PV
    dim3 gfa(SEQ / QB, BATCH * HEADS);
    fused_attn<<<gfa, blk, SMEM_BYTES>>>(gq, gk, gv, mask, attn, go);

    // output projection
    dim3 gout(DMODEL / 128, TOK / 128, 1);
    proj_gemm<0><<<gout, blk, PJ_SMEM_BYTES>>>(go, go, go, Wo, Wo, Wo, bo, bo, bo, out, out, out);
}

// round 8
// speedup vs baseline: 1.1601x; 1.0424x over previous
#include <cuda_runtime.h>
#include <cstdint>

#define BATCH   4
#define HEADS   16
#define SEQ     2048
#define DMODEL  1024
#define HDIM    64
#define TOK     (BATCH*SEQ)       // 8192
// softmax in exp2 domain: scale = (1/sqrt(64)) * log2(e)
#define SCALE2  0.18033688011112042f

#define QB      128               // query rows per fused block
#define TC      64                // key tile

// -------- scratch (allocation-free rule: __device__ globals) --------
__device__ float g_Q[BATCH*HEADS*SEQ*HDIM];   // [b][h][l][dh]  (tf32-rounded)
__device__ float g_K[BATCH*HEADS*SEQ*HDIM];   // (tf32-rounded)
__device__ float g_V[BATCH*HEADS*SEQ*HDIM];   // (tf32-rounded)
__device__ float g_O[TOK*DMODEL];             // [b*l][h*64+dh]

__device__ __forceinline__ float to_tf32(float x) {
    float r;
    asm("cvt.rna.tf32.f32 %0, %1;" : "=f"(r) : "f"(x));
    return r;
}

__device__ __forceinline__ float ex2(float x) {
    float r;
    asm("ex2.approx.f32 %0, %1;" : "=f"(r) : "f"(x));
    return r;
}

__device__ __forceinline__ void mma_tf32(float c[4],
    uint32_t a0, uint32_t a1, uint32_t a2, uint32_t a3,
    uint32_t b0, uint32_t b1)
{
    asm volatile(
        "mma.sync.aligned.m16n8k8.row.col.f32.tf32.tf32.f32 "
        "{%0,%1,%2,%3}, {%4,%5,%6,%7}, {%8,%9}, {%0,%1,%2,%3};\n"
        : "+f"(c[0]), "+f"(c[1]), "+f"(c[2]), "+f"(c[3])
        : "r"(a0), "r"(a1), "r"(a2), "r"(a3), "r"(b0), "r"(b1));
}

__device__ __forceinline__ uint32_t smem_u32(const void* p) {
    uint32_t a;
    asm("{ .reg .u64 t; cvta.to.shared.u64 t, %1; cvt.u32.u64 %0, t; }"
        : "=r"(a) : "l"(p));
    return a;
}

__device__ __forceinline__ void cp16(uint32_t dst, const float* src) {
    asm volatile("cp.async.cg.shared.global [%0], [%1], 16;" :: "r"(dst), "l"(src));
}
__device__ __forceinline__ void cp_commit() {
    asm volatile("cp.async.commit_group;" ::: "memory");
}
__device__ __forceinline__ void cp_wait1() {
    asm volatile("cp.async.wait_group 1;" ::: "memory");
}

#define NEG_INF __int_as_float(0xff800000)

// ============================================================================
// Software-pipelined projection GEMM (double-buffered smem, 1 sync/iter).
// C[8192x1024] = A @ W + bias.  EPI 0: row-major out (fp32).
// EPI 1: head scatter, tf32-rounded output (consumed by fused_attn mma).
// grid.z selects (A, W, bias, out) triple for merged QKV launch.
// ============================================================================
#define PJ_AS(buf)  (smf + (buf) * 4608)
#define PJ_BS(buf)  (smf + 9216 + (buf) * 4224)
#define PJ_SMEM_BYTES 70656

template<int EPI>
__global__ void __launch_bounds__(256, 2)
proj_gemm(const float* __restrict__ A0, const float* __restrict__ A1,
          const float* __restrict__ A2,
          const float* __restrict__ W0, const float* __restrict__ W1,
          const float* __restrict__ W2,
          const float* __restrict__ b0, const float* __restrict__ b1,
          const float* __restrict__ b2,
          float* __restrict__ o0, float* __restrict__ o1, float* __restrict__ o2)
{
    extern __shared__ float smf[];

    const int z = blockIdx.z;
    const float* Ag   = (z == 0) ? A0 : (z == 1) ? A1 : A2;
    const float* Wg   = (z == 0) ? W0 : (z == 1) ? W1 : W2;
    const float* bias = (z == 0) ? b0 : (z == 1) ? b1 : b2;
    float* out        = (z == 0) ? o0 : (z == 1) ? o1 : o2;

    const int tid  = threadIdx.x;
    const int warp = tid >> 5;
    const int lane = tid & 31;
    const int wm   = warp & 3;          // 0..3 (M)
    const int wn   = warp >> 2;         // 0..1 (N)
    const int g    = lane >> 2;
    const int t4   = lane & 3;

    const int bn = blockIdx.x * 128;
    const int bm = blockIdx.y * 128;

    float acc[2][8][4];
    #pragma unroll
    for (int mi = 0; mi < 2; ++mi)
        #pragma unroll
        for (int ni = 0; ni < 8; ++ni)
            #pragma unroll
            for (int e = 0; e < 4; ++e) acc[mi][ni][e] = 0.f;

    // ---- prologue: stage tile 0 ----
    {
        float* As = PJ_AS(0);
        float* Bs = PJ_BS(0);
        #pragma unroll
        for (int j = 0; j < 4; ++j) {
            int lin = j * 256 + tid;
            int row = lin >> 3, c4 = (lin & 7) * 4;
            float4 x = *(const float4*)(Ag + (size_t)(bm + row) * DMODEL + c4);
            x.x = to_tf32(x.x); x.y = to_tf32(x.y);
            x.z = to_tf32(x.z); x.w = to_tf32(x.w);
            *(float4*)(As + row * 36 + c4) = x;
        }
        #pragma unroll
        for (int j = 0; j < 4; ++j) {
            int lin = j * 256 + tid;
            int row = lin >> 5, c4 = (lin & 31) * 4;
            float4 x = *(const float4*)(Wg + (size_t)row * DMODEL + bn + c4);
            x.x = to_tf32(x.x); x.y = to_tf32(x.y);
            x.z = to_tf32(x.z); x.w = to_tf32(x.w);
            *(float4*)(Bs + row * 132 + c4) = x;
        }
    }
    __syncthreads();

    for (int t = 0; t < 32; ++t) {
        const int cur = t & 1, nxt = cur ^ 1;
        float* Ac = PJ_AS(cur);
        float* Bc = PJ_BS(cur);
        float* An = PJ_AS(nxt);
        float* Bn = PJ_BS(nxt);
        const int kt = (t < 31) ? (t + 1) : 31;
        const int kg = kt * 32;

        float4 ra[4];
        #pragma unroll
        for (int j = 0; j < 4; ++j) {
            int lin = j * 256 + tid;
            int row = lin >> 3, c4 = (lin & 7) * 4;
            ra[j] = *(const float4*)(Ag + (size_t)(bm + row) * DMODEL + kg + c4);
        }

        #pragma unroll
        for (int kh = 0; kh < 2; ++kh) {
            const int kk = kh * 8;
            uint32_t af[2][4];
            uint32_t bf[8][2];
            #pragma unroll
            for (int mi = 0; mi < 2; ++mi) {
                int r = wm * 32 + mi * 16;
                af[mi][0] = __float_as_uint(Ac[(r + g    ) * 36 + kk + t4    ]);
                af[mi][1] = __float_as_uint(Ac[(r + g + 8) * 36 + kk + t4    ]);
                af[mi][2] = __float_as_uint(Ac[(r + g    ) * 36 + kk + t4 + 4]);
                af[mi][3] = __float_as_uint(Ac[(r + g + 8) * 36 + kk + t4 + 4]);
            }
            #pragma unroll
            for (int ni = 0; ni < 8; ++ni) {
                int c = wn * 64 + ni * 8 + g;
                bf[ni][0] = __float_as_uint(Bc[(kk + t4    ) * 132 + c]);
                bf[ni][1] = __float_as_uint(Bc[(kk + t4 + 4) * 132 + c]);
            }
            #pragma unroll
            for (int mi = 0; mi < 2; ++mi)
                #pragma unroll
                for (int ni = 0; ni < 8; ++ni)
                    mma_tf32(acc[mi][ni], af[mi][0], af[mi][1], af[mi][2], af[mi][3],
                             bf[ni][0], bf[ni][1]);
        }

        #pragma unroll
        for (int j = 0; j < 4; ++j) {
            int lin = j * 256 + tid;
            int row = lin >> 3, c4 = (lin & 7) * 4;
            float4 x = ra[j];
            x.x = to_tf32(x.x); x.y = to_tf32(x.y);
            x.z = to_tf32(x.z); x.w = to_tf32(x.w);
            *(float4*)(An + row * 36 + c4) = x;
        }

        float4 rb[4];
        #pragma unroll
        for (int j = 0; j < 4; ++j) {
            int lin = j * 256 + tid;
            int row = lin >> 5, c4 = (lin & 31) * 4;
            rb[j] = *(const float4*)(Wg + (size_t)(kg + row) * DMODEL + bn + c4);
        }

        #pragma unroll
        for (int kh = 0; kh < 2; ++kh) {
            const int kk = 16 + kh * 8;
            uint32_t af[2][4];
            uint32_t bf[8][2];
            #pragma unroll
            for (int mi = 0; mi < 2; ++mi) {
                int r = wm * 32 + mi * 16;
                af[mi][0] = __float_as_uint(Ac[(r + g    ) * 36 + kk + t4    ]);
                af[mi][1] = __float_as_uint(Ac[(r + g + 8) * 36 + kk + t4    ]);
                af[mi][2] = __float_as_uint(Ac[(r + g    ) * 36 + kk + t4 + 4]);
                af[mi][3] = __float_as_uint(Ac[(r + g + 8) * 36 + kk + t4 + 4]);
            }
            #pragma unroll
            for (int ni = 0; ni < 8; ++ni) {
                int c = wn * 64 + ni * 8 + g;
                bf[ni][0] = __float_as_uint(Bc[(kk + t4    ) * 132 + c]);
                bf[ni][1] = __float_as_uint(Bc[(kk + t4 + 4) * 132 + c]);
            }
            #pragma unroll
            for (int mi = 0; mi < 2; ++mi)
                #pragma unroll
                for (int ni = 0; ni < 8; ++ni)
                    mma_tf32(acc[mi][ni], af[mi][0], af[mi][1], af[mi][2], af[mi][3],
                             bf[ni][0], bf[ni][1]);
        }

        #pragma unroll
        for (int j = 0; j < 4; ++j) {
            int lin = j * 256 + tid;
            int row = lin >> 5, c4 = (lin & 31) * 4;
            float4 x = rb[j];
            x.x = to_tf32(x.x); x.y = to_tf32(x.y);
            x.z = to_tf32(x.z); x.w = to_tf32(x.w);
            *(float4*)(Bn + row * 132 + c4) = x;
        }
        __syncthreads();
    }

    // ---- epilogue ----
    #pragma unroll
    for (int mi = 0; mi < 2; ++mi) {
        #pragma unroll
        for (int ni = 0; ni < 8; ++ni) {
            #pragma unroll
            for (int e = 0; e < 4; ++e) {
                int row = bm + wm * 32 + mi * 16 + g + ((e >= 2) ? 8 : 0);
                int col = bn + wn * 64 + ni * 8 + t4 * 2 + (e & 1);
                float v = acc[mi][ni][e] + bias[col];
                if (EPI == 0) {
                    out[(size_t)row * DMODEL + col] = v;
                } else {
                    // pre-round to tf32 here (numerically identical to rounding
                    // at fused_attn staging; enables cvt-free cp.async there)
                    v = to_tf32(v);
                    int b  = row >> 11;
                    int l  = row & (SEQ - 1);
                    int h  = col >> 6;
                    int dh = col & (HDIM - 1);
                    out[(((size_t)(b * HEADS + h)) * SEQ + l) * HDIM + dh] = v;
                }
            }
        }
    }
}

// ============================================================================
// Fused attention v4: cp.async double-buffered K/V staging (inputs already
// tf32-rounded). pass 1 = QK^T + online stats; pass 2 = recompute QK^T,
// normalize, direct attn write, PV via shuffle A-frags. 2 CTAs/SM.
// smem floats: Ks0 @0 | Ks1 @4352 | Vs0 @8704 | Vs1 @13312 | Mf @17920
// Qs[128][68] (8704 floats) overlays Ks0+Ks1 during init only.
// ============================================================================
#define KS0      0
#define KS1      4352
#define VS0      8704
#define VS1      13312
#define MASK_OFF 17920
#define SMEM_FLOATS 19968
#define SMEM_BYTES  (SMEM_FLOATS*4)

__global__ void __launch_bounds__(256, 2)
fused_attn(const float* __restrict__ gQ, const float* __restrict__ gK,
           const float* __restrict__ gV, const int* __restrict__ mask,
           float* __restrict__ attnOut, float* __restrict__ gO)
{
    extern __shared__ float sm[];
    float* Qs = sm;               // overlay on Ks0+Ks1, dead after aq extraction
    float* Mf = sm + MASK_OFF;
    const uint32_t sb = smem_u32(sm);

    const int tid  = threadIdx.x;
    const int lane = tid & 31;
    const int warp = tid >> 5;
    const int g    = lane >> 2;
    const int t4   = lane & 3;
    const int wrow = warp * 16;

    const int qb = blockIdx.x * QB;
    const int bh = blockIdx.y;
    const int zb = bh >> 4;
    const int zh = bh & 15;

    const float* Q = gQ + ((size_t)bh * SEQ + qb) * HDIM;
    const float* K = gK + (size_t)bh * SEQ * HDIM;
    const float* V = gV + (size_t)bh * SEQ * HDIM;
    float* attn = attnOut + ((size_t)(zh * BATCH + zb) * SEQ + qb) * SEQ;

    // mask -> additive float
    #pragma unroll
    for (int i = 0; i < SEQ / 256; ++i) {
        int c = i * 256 + tid;
        Mf[c] = mask[zb * SEQ + c] ? NEG_INF : 0.f;
    }
    // Q tile -> smem (already tf32-valued)
    #pragma unroll
    for (int i = 0; i < 8; ++i) {
        int idx = i * 256 + tid;
        int r = idx >> 4, c4 = (idx & 15) << 2;
        *(float4*)(Qs + r * 68 + c4) = *(const float4*)(Q + (size_t)r * HDIM + c4);
    }
    __syncthreads();

    uint32_t aq[8][4];
    #pragma unroll
    for (int kk8 = 0; kk8 < 8; ++kk8) {
        int kk = kk8 * 8;
        aq[kk8][0] = __float_as_uint(Qs[(wrow + g    ) * 68 + kk + t4    ]);
        aq[kk8][1] = __float_as_uint(Qs[(wrow + g + 8) * 68 + kk + t4    ]);
        aq[kk8][2] = __float_as_uint(Qs[(wrow + g    ) * 68 + kk + t4 + 4]);
        aq[kk8][3] = __float_as_uint(Qs[(wrow + g + 8) * 68 + kk + t4 + 4]);
    }
    __syncthreads();   // Qs fully consumed before cp.async reuses the region

    // cp.async stagers (K rows padded to 68, V rows padded to 72)
    auto issueK = [&](int t, int buf) {
        const float* Kt = K + (size_t)t * TC * HDIM;
        const uint32_t base = sb + (buf ? KS1 : KS0) * 4;
        #pragma unroll
        for (int i = 0; i < 4; ++i) {
            int idx = i * 256 + tid;
            int r = idx >> 4, c4 = (idx & 15) << 2;
            cp16(base + (r * 68 + c4) * 4, Kt + r * HDIM + c4);
        }
    };
    auto issueV = [&](int t, int buf) {
        const float* Vt = V + (size_t)t * TC * HDIM;
        const uint32_t base = sb + (buf ? VS1 : VS0) * 4;
        #pragma unroll
        for (int i = 0; i < 4; ++i) {
            int idx = i * 256 + tid;
            int r = idx >> 4, c4 = (idx & 15) << 2;
            cp16(base + (r * 72 + c4) * 4, Vt + r * HDIM + c4);
        }
    };

    // ---------------- pass 1: online (m, l) ----------------
    float m0 = NEG_INF, m1 = NEG_INF, l0 = 0.f, l1 = 0.f;

    issueK(0, 0); cp_commit();
    for (int t = 0; t < SEQ / TC; ++t) {
        __syncthreads();                       // nxt buffer free (prev readers done)
        if (t + 1 < SEQ / TC) issueK(t + 1, (t + 1) & 1);
        cp_commit();
        cp_wait1();                            // tile t arrived (this thread)
        __syncthreads();                       // publish arrivals across warps
        const float* Ks = sm + ((t & 1) ? KS1 : KS0);

        float sacc[8][4];
        #pragma unroll
        for (int nt = 0; nt < 8; ++nt)
            #pragma unroll
            for (int e = 0; e < 4; ++e) sacc[nt][e] = 0.f;

        #pragma unroll
        for (int kk8 = 0; kk8 < 8; ++kk8) {
            int kk = kk8 * 8;
            #pragma unroll
            for (int nt = 0; nt < 8; ++nt) {
                uint32_t b0 = __float_as_uint(Ks[(nt * 8 + g) * 68 + kk + t4    ]);
                uint32_t b1 = __float_as_uint(Ks[(nt * 8 + g) * 68 + kk + t4 + 4]);
                mma_tf32(sacc[nt], aq[kk8][0], aq[kk8][1], aq[kk8][2], aq[kk8][3], b0, b1);
            }
        }

        float tm0 = NEG_INF, tm1 = NEG_INF;
        #pragma unroll
        for (int nt = 0; nt < 8; ++nt) {
            float mk0 = Mf[t * TC + nt * 8 + t4 * 2];
            float mk1 = Mf[t * TC + nt * 8 + t4 * 2 + 1];
            sacc[nt][0] = sacc[nt][0] * SCALE2 + mk0;
            sacc[nt][1] = sacc[nt][1] * SCALE2 + mk1;
            sacc[nt][2] = sacc[nt][2] * SCALE2 + mk0;
            sacc[nt][3] = sacc[nt][3] * SCALE2 + mk1;
            tm0 = fmaxf(tm0, fmaxf(sacc[nt][0], sacc[nt][1]));
            tm1 = fmaxf(tm1, fmaxf(sacc[nt][2], sacc[nt][3]));
        }
        tm0 = fmaxf(tm0, __shfl_xor_sync(0xffffffffu, tm0, 1));
        tm0 = fmaxf(tm0, __shfl_xor_sync(0xffffffffu, tm0, 2));
        tm1 = fmaxf(tm1, __shfl_xor_sync(0xffffffffu, tm1, 1));
        tm1 = fmaxf(tm1, __shfl_xor_sync(0xffffffffu, tm1, 2));

        float mn0 = fmaxf(m0, tm0), mn1 = fmaxf(m1, tm1);
        float ms0 = (mn0 == NEG_INF) ? 0.f : mn0;
        float ms1 = (mn1 == NEG_INF) ? 0.f : mn1;

        float sum0 = 0.f, sum1 = 0.f;
        #pragma unroll
        for (int nt = 0; nt < 8; ++nt) {
            sum0 += ex2(sacc[nt][0] - ms0) + ex2(sacc[nt][1] - ms0);
            sum1 += ex2(sacc[nt][2] - ms1) + ex2(sacc[nt][3] - ms1);
        }
        sum0 += __shfl_xor_sync(0xffffffffu, sum0, 1);
        sum0 += __shfl_xor_sync(0xffffffffu, sum0, 2);
        sum1 += __shfl_xor_sync(0xffffffffu, sum1, 1);
        sum1 += __shfl_xor_sync(0xffffffffu, sum1, 2);

        float a0 = (m0 == NEG_INF) ? 0.f : ex2(m0 - ms0);
        float a1 = (m1 == NEG_INF) ? 0.f : ex2(m1 - ms1);
        l0 = l0 * a0 + sum0;
        l1 = l1 * a1 + sum1;
        m0 = mn0; m1 = mn1;
    }

    const float invl0 = (l0 > 0.f) ? 1.f / l0 : 0.f;
    const float invl1 = (l1 > 0.f) ? 1.f / l1 : 0.f;
    const float mf0 = (m0 == NEG_INF) ? 0.f : m0;
    const float mf1 = (m1 == NEG_INF) ? 0.f : m1;

    // ---------------- pass 2: recompute + P write + PV ----------------
    float oacc[8][4];
    #pragma unroll
    for (int nt = 0; nt < 8; ++nt)
        #pragma unroll
        for (int e = 0; e < 4; ++e) oacc[nt][e] = 0.f;

    const int srcA = (lane & ~3) | (t4 >> 1);   // col t4   source lane
    const int srcB = srcA + 2;                  // col t4+4 source lane
    const bool odd = (t4 & 1);

    issueK(0, 0); issueV(0, 0); cp_commit();
    for (int t = 0; t < SEQ / TC; ++t) {
        __syncthreads();
        if (t + 1 < SEQ / TC) { issueK(t + 1, (t + 1) & 1); issueV(t + 1, (t + 1) & 1); }
        cp_commit();
        cp_wait1();
        __syncthreads();
        const float* Ks = sm + ((t & 1) ? KS1 : KS0);
        const float* Vs = sm + ((t & 1) ? VS1 : VS0);

        float sacc[8][4];
        #pragma unroll
        for (int nt = 0; nt < 8; ++nt)
            #pragma unroll
            for (int e = 0; e < 4; ++e) sacc[nt][e] = 0.f;

        #pragma unroll
        for (int kk8 = 0; kk8 < 8; ++kk8) {
            int kk = kk8 * 8;
            #pragma unroll
            for (int nt = 0; nt < 8; ++nt) {
                uint32_t b0 = __float_as_uint(Ks[(nt * 8 + g) * 68 + kk + t4    ]);
                uint32_t b1 = __float_as_uint(Ks[(nt * 8 + g) * 68 + kk + t4 + 4]);
                mma_tf32(sacc[nt], aq[kk8][0], aq[kk8][1], aq[kk8][2], aq[kk8][3], b0, b1);
            }
        }

        // normalize in place + direct attn write (float2, sector-aligned)
        #pragma unroll
        for (int nt = 0; nt < 8; ++nt) {
            float mk0 = Mf[t * TC + nt * 8 + t4 * 2];
            float mk1 = Mf[t * TC + nt * 8 + t4 * 2 + 1];
            sacc[nt][0] = ex2(sacc[nt][0] * SCALE2 + mk0 - mf0) * invl0;
            sacc[nt][1] = ex2(sacc[nt][1] * SCALE2 + mk1 - mf0) * invl0;
            sacc[nt][2] = ex2(sacc[nt][2] * SCALE2 + mk0 - mf1) * invl1;
            sacc[nt][3] = ex2(sacc[nt][3] * SCALE2 + mk1 - mf1) * invl1;
            float* d0 = attn + (size_t)(wrow + g) * SEQ + t * TC + nt * 8 + t4 * 2;
            *(float2*)d0 = make_float2(sacc[nt][0], sacc[nt][1]);
            *(float2*)(d0 + 8 * SEQ) = make_float2(sacc[nt][2], sacc[nt][3]);
        }

        // PV: A-fragments from sacc via lane shuffles (C->A layout permute)
        #pragma unroll
        for (int kt = 0; kt < 8; ++kt) {
            float x0 = __shfl_sync(0xffffffffu, sacc[kt][0], srcA);
            float x1 = __shfl_sync(0xffffffffu, sacc[kt][1], srcA);
            float y0 = __shfl_sync(0xffffffffu, sacc[kt][0], srcB);
            float y1 = __shfl_sync(0xffffffffu, sacc[kt][1], srcB);
            float z0 = __shfl_sync(0xffffffffu, sacc[kt][2], srcA);
            float z1 = __shfl_sync(0xffffffffu, sacc[kt][3], srcA);
            float w0 = __shfl_sync(0xffffffffu, sacc[kt][2], srcB);
            float w1 = __shfl_sync(0xffffffffu, sacc[kt][3], srcB);
            uint32_t a0 = __float_as_uint(to_tf32(odd ? x1 : x0));
            uint32_t a1 = __float_as_uint(to_tf32(odd ? z1 : z0));
            uint32_t a2 = __float_as_uint(to_tf32(odd ? y1 : y0));
            uint32_t a3 = __float_as_uint(to_tf32(odd ? w1 : w0));
            int kb = kt * 8;
            #pragma unroll
            for (int nt = 0; nt < 8; ++nt) {
                uint32_t b0 = __float_as_uint(Vs[(kb + t4    ) * 72 + nt * 8 + g]);
                uint32_t b1 = __float_as_uint(Vs[(kb + t4 + 4) * 72 + nt * 8 + g]);
                mma_tf32(oacc[nt], a0, a1, a2, a3, b0, b1);
            }
        }
    }

    // write O block to g_O [b*l][h*64+dv]
    #pragma unroll
    for (int nt = 0; nt < 8; ++nt) {
        #pragma unroll
        for (int e = 0; e < 4; ++e) {
            int rl  = wrow + g + ((e >= 2) ? 8 : 0);
            int col = nt * 8 + t4 * 2 + (e & 1);
            gO[((size_t)zb * SEQ + qb + rl) * DMODEL + zh * HDIM + col] = oacc[nt][e];
        }
    }
}

// ============================================================================
extern "C" void kernel_launch(void* const* d_in, const int* in_sizes, int n_in,
                              void* d_out, int out_size)
{
    const float* q    = (const float*)d_in[0];
    const float* k    = (const float*)d_in[1];
    const float* v    = (const float*)d_in[2];
    const int*   mask = (const int*)d_in[3];
    const float* Wq = (const float*)d_in[4];
    const float* bq = (const float*)d_in[5];
    const float* Wk = (const float*)d_in[6];
    const float* bk = (const float*)d_in[7];
    const float* Wv = (const float*)d_in[8];
    const float* bv = (const float*)d_in[9];
    const float* Wo = (const float*)d_in[10];
    const float* bo = (const float*)d_in[11];

    float* out  = (float*)d_out;                         // [4,2048,1024]
    float* attn = out + (size_t)TOK * DMODEL;            // [16,4,2048,2048]

    float *gq, *gk, *gv, *go;
    cudaGetSymbolAddress((void**)&gq, g_Q);
    cudaGetSymbolAddress((void**)&gk, g_K);
    cudaGetSymbolAddress((void**)&gv, g_V);
    cudaGetSymbolAddress((void**)&go, g_O);

    static int attr_set = 0;
    if (!attr_set) {
        cudaFuncSetAttribute(proj_gemm<0>, cudaFuncAttributeMaxDynamicSharedMemorySize, PJ_SMEM_BYTES);
        cudaFuncSetAttribute(proj_gemm<1>, cudaFuncAttributeMaxDynamicSharedMemorySize, PJ_SMEM_BYTES);
        cudaFuncSetAttribute(fused_attn, cudaFuncAttributeMaxDynamicSharedMemorySize, SMEM_BYTES);
        attr_set = 1;
    }

    dim3 blk(256);

    // merged Q/K/V projections (z selects input/weight/output)
    dim3 gqkv(DMODEL / 128, TOK / 128, 3);
    proj_gemm<1><<<gqkv, blk, PJ_SMEM_BYTES>>>(q, k, v, Wq, Wk, Wv, bq, bk, bv, gq, gk, gv);

    // fused scores + softmax + attn-write + PV
    dim3 gfa(SEQ / QB, BATCH * HEADS);
    fused_attn<<<gfa, blk, SMEM_BYTES>>>(gq, gk, gv, mask, attn, go);

    // output projection
    dim3 gout(DMODEL / 128, TOK / 128, 1);
    proj_gemm<0><<<gout, blk, PJ_SMEM_BYTES>>>(go, go, go, Wo, Wo, Wo, bo, bo, bo, out, out, out);
}

// round 9
// speedup vs baseline: 1.9236x; 1.6580x over previous
#include <cuda_runtime.h>
#include <cuda_fp16.h>
#include <cstdint>

#define BATCH   4
#define HEADS   16
#define SEQ     2048
#define DMODEL  1024
#define HDIM    64
#define TOK     (BATCH*SEQ)       // 8192
// softmax in exp2 domain: scale = (1/sqrt(64)) * log2(e)
#define SCALE2  0.18033688011112042f

#define QB      128               // query rows per fused block
#define TC      64                // key tile

// -------- scratch (allocation-free rule: __device__ globals) --------
__device__ __half g_Q[BATCH*HEADS*SEQ*HDIM];   // [b][h][l][dh]
__device__ __half g_K[BATCH*HEADS*SEQ*HDIM];   // [b][h][t][dh]
__device__ __half g_V[BATCH*HEADS*SEQ*HDIM];   // [b][h][dh][t]  (transposed!)
__device__ __half g_O[TOK*DMODEL];             // [b*l][h*64+dv]

__device__ __forceinline__ float ex2(float x) {
    float r;
    asm("ex2.approx.f32 %0, %1;" : "=f"(r) : "f"(x));
    return r;
}

__device__ __forceinline__ uint32_t f2h2(float lo, float hi) {
    __half2 h = __floats2half2_rn(lo, hi);
    return *reinterpret_cast<uint32_t*>(&h);
}

__device__ __forceinline__ void mma_f16(float c[4],
    uint32_t a0, uint32_t a1, uint32_t a2, uint32_t a3,
    uint32_t b0, uint32_t b1)
{
    asm volatile(
        "mma.sync.aligned.m16n8k16.row.col.f32.f16.f16.f32 "
        "{%0,%1,%2,%3}, {%4,%5,%6,%7}, {%8,%9}, {%0,%1,%2,%3};\n"
        : "+f"(c[0]), "+f"(c[1]), "+f"(c[2]), "+f"(c[3])
        : "r"(a0), "r"(a1), "r"(a2), "r"(a3), "r"(b0), "r"(b1));
}

__device__ __forceinline__ void ldsm_x4(uint32_t r[4], uint32_t addr) {
    asm volatile("ldmatrix.sync.aligned.m8n8.x4.shared.b16 {%0,%1,%2,%3}, [%4];"
        : "=r"(r[0]), "=r"(r[1]), "=r"(r[2]), "=r"(r[3]) : "r"(addr));
}
__device__ __forceinline__ void ldsm_x4_t(uint32_t r[4], uint32_t addr) {
    asm volatile("ldmatrix.sync.aligned.m8n8.x4.trans.shared.b16 {%0,%1,%2,%3}, [%4];"
        : "=r"(r[0]), "=r"(r[1]), "=r"(r[2]), "=r"(r[3]) : "r"(addr));
}

__device__ __forceinline__ uint32_t smem_u32(const void* p) {
    uint32_t a;
    asm("{ .reg .u64 t; cvta.to.shared.u64 t, %1; cvt.u32.u64 %0, t; }"
        : "=r"(a) : "l"(p));
    return a;
}
__device__ __forceinline__ void cp16(uint32_t dst, const void* src) {
    asm volatile("cp.async.cg.shared.global [%0], [%1], 16;" :: "r"(dst), "l"(src));
}
__device__ __forceinline__ void cp_commit() {
    asm volatile("cp.async.commit_group;" ::: "memory");
}
__device__ __forceinline__ void cp_wait1() {
    asm volatile("cp.async.wait_group 1;" ::: "memory");
}

#define NEG_INF __int_as_float(0xff800000)

// ============================================================================
// fp16 projection GEMM, software-pipelined, double-buffered, ldmatrix frags.
// C[8192x1024] = A @ W + bias.
//  EPI 0: fp32 row-major out (final projection), A source fp16 (AHALF=1).
//  EPI 1: fp16 scatter out. z<2 -> [b][h][l][dh]; z==2 -> V transposed
//         [b][h][dh][t]. A source fp32 (AHALF=0).
// smem halves: As0@0 [128][40] | As1@5120 | Bs0@10240 [32][136] | Bs1@14592
// total 18944 halves = 37888 B.
// ============================================================================
#define PAS 40
#define PBS 136
#define PJ_AS_H(buf) ((buf) ? 5120 : 0)
#define PJ_BS_H(buf) ((buf) ? 14592 : 10240)
#define PJ_SMEM_BYTES 37888

template<int EPI, int AHALF>
__global__ void __launch_bounds__(256, 2)
proj_gemm(const void* A0v, const void* A1v, const void* A2v,
          const float* __restrict__ W0, const float* __restrict__ W1,
          const float* __restrict__ W2,
          const float* __restrict__ b0, const float* __restrict__ b1,
          const float* __restrict__ b2,
          void* o0v, void* o1v, void* o2v)
{
    extern __shared__ char smc[];
    __half* smh = (__half*)smc;
    const uint32_t sb = smem_u32(smc);

    const int z = blockIdx.z;
    const void*  Av   = (z == 0) ? A0v : (z == 1) ? A1v : A2v;
    const float* Wg   = (z == 0) ? W0 : (z == 1) ? W1 : W2;
    const float* bias = (z == 0) ? b0 : (z == 1) ? b1 : b2;
    void* outv        = (z == 0) ? o0v : (z == 1) ? o1v : o2v;

    const int tid  = threadIdx.x;
    const int warp = tid >> 5;
    const int lane = tid & 31;
    const int wm   = warp & 3;          // 0..3 (M)
    const int wn   = warp >> 2;         // 0..1 (N)
    const int g    = lane >> 2;
    const int t4   = lane & 3;
    const int l15  = lane & 15;
    const int lhi  = (lane >> 4) * 8;

    const int bn = blockIdx.x * 128;
    const int bm = blockIdx.y * 128;

    float acc[2][8][4];
    #pragma unroll
    for (int mi = 0; mi < 2; ++mi)
        #pragma unroll
        for (int ni = 0; ni < 8; ++ni)
            #pragma unroll
            for (int e = 0; e < 4; ++e) acc[mi][ni][e] = 0.f;

    // ---- staging helpers ----
    const float* Af = (const float*)Av;      // AHALF==0
    const __half* Ah = (const __half*)Av;    // AHALF==1

    auto stageA = [&](int kg, int buf) {
        __half* As = smh + PJ_AS_H(buf);
        if (AHALF) {
            #pragma unroll
            for (int i = 0; i < 2; ++i) {
                int idx = i * 256 + tid;
                int r = idx >> 2, c = idx & 3;
                *(uint4*)(As + r * PAS + c * 8) =
                    *(const uint4*)(Ah + (size_t)(bm + r) * DMODEL + kg + c * 8);
            }
        } else {
            #pragma unroll
            for (int i = 0; i < 4; ++i) {
                int idx = i * 256 + tid;
                int r = idx >> 3, c4 = (idx & 7) * 4;
                float4 x = *(const float4*)(Af + (size_t)(bm + r) * DMODEL + kg + c4);
                uint2 s; s.x = f2h2(x.x, x.y); s.y = f2h2(x.z, x.w);
                *(uint2*)(As + r * PAS + c4) = s;
            }
        }
    };
    auto stageB = [&](int kg, int buf) {
        __half* Bs = smh + PJ_BS_H(buf);
        #pragma unroll
        for (int i = 0; i < 4; ++i) {
            int idx = i * 256 + tid;
            int r = idx >> 5, c4 = (idx & 31) * 4;
            float4 x = *(const float4*)(Wg + (size_t)(kg + r) * DMODEL + bn + c4);
            uint2 s; s.x = f2h2(x.x, x.y); s.y = f2h2(x.z, x.w);
            *(uint2*)(Bs + r * PBS + c4) = s;
        }
    };

    auto compute = [&](int buf, int kk) {
        const uint32_t asb = sb + PJ_AS_H(buf) * 2;
        const uint32_t bsb = sb + PJ_BS_H(buf) * 2;
        uint32_t af[2][4];
        #pragma unroll
        for (int mi = 0; mi < 2; ++mi)
            ldsm_x4(af[mi], asb + ((wm * 32 + mi * 16 + l15) * PAS + kk + lhi) * 2);
        uint32_t bf[4][4];
        #pragma unroll
        for (int p = 0; p < 4; ++p)
            ldsm_x4_t(bf[p], bsb + ((kk + l15) * PBS + wn * 64 + p * 16 + lhi) * 2);
        #pragma unroll
        for (int mi = 0; mi < 2; ++mi)
            #pragma unroll
            for (int p = 0; p < 4; ++p) {
                mma_f16(acc[mi][2 * p    ], af[mi][0], af[mi][1], af[mi][2], af[mi][3],
                        bf[p][0], bf[p][1]);
                mma_f16(acc[mi][2 * p + 1], af[mi][0], af[mi][1], af[mi][2], af[mi][3],
                        bf[p][2], bf[p][3]);
            }
    };

    // ---- prologue ----
    stageA(0, 0);
    stageB(0, 0);
    __syncthreads();

    for (int t = 0; t < 32; ++t) {
        const int cur = t & 1, nxt = cur ^ 1;
        const int kt = (t < 31) ? (t + 1) : 31;
        const int kg = kt * 32;

        // prefetch+compute interleave (register prefetch via lambda re-stage:
        // stageA/B read gmem then STS; placed between compute halves)
        compute(cur, 0);
        stageA(kg, nxt);
        compute(cur, 16);
        stageB(kg, nxt);
        __syncthreads();
    }

    // ---- epilogue ----
    #pragma unroll
    for (int mi = 0; mi < 2; ++mi) {
        #pragma unroll
        for (int ni = 0; ni < 8; ++ni) {
            int row0 = bm + wm * 32 + mi * 16 + g;
            int col  = bn + wn * 64 + ni * 8 + t4 * 2;
            float v00 = acc[mi][ni][0] + bias[col];
            float v01 = acc[mi][ni][1] + bias[col + 1];
            float v10 = acc[mi][ni][2] + bias[col];
            float v11 = acc[mi][ni][3] + bias[col + 1];
            if (EPI == 0) {
                float* out = (float*)outv;
                *(float2*)(out + (size_t)row0 * DMODEL + col) = make_float2(v00, v01);
                *(float2*)(out + (size_t)(row0 + 8) * DMODEL + col) = make_float2(v10, v11);
            } else {
                __half* out = (__half*)outv;
                int h  = col >> 6;
                int dh = col & 63;
                if (z < 2) {
                    #pragma unroll
                    for (int rr = 0; rr < 2; ++rr) {
                        int row = row0 + rr * 8;
                        int b = row >> 11, l = row & (SEQ - 1);
                        uint32_t pv = rr ? f2h2(v10, v11) : f2h2(v00, v01);
                        *(uint32_t*)(out + (((size_t)(b * HEADS + h)) * SEQ + l) * HDIM + dh) = pv;
                    }
                } else {
                    // V transposed: [b][h][dh][t]
                    #pragma unroll
                    for (int rr = 0; rr < 2; ++rr) {
                        int row = row0 + rr * 8;
                        int b = row >> 11, l = row & (SEQ - 1);
                        float va = rr ? v10 : v00;
                        float vb = rr ? v11 : v01;
                        size_t base = ((size_t)(b * HEADS + h)) * HDIM;
                        out[(base + dh    ) * SEQ + l] = __float2half_rn(va);
                        out[(base + dh + 1) * SEQ + l] = __float2half_rn(vb);
                    }
                }
            }
        }
    }
}

// ============================================================================
// Fused attention fp16: pass 1 = QK^T + online stats; pass 2 = recompute,
// normalize, fp32 attn write, PV with A-frags straight from sacc (C==A layout).
// smem halves: KS0@0 | KS1@4608 | VS0@9216 | VS1@13824  ([64][72] each)
// Mf fp32 @ byte 36864 (2048 floats). Qs[128][72] overlays KS/VS during init.
// total 45056 B.
// ============================================================================
#define FST 72
#define KS0H 0
#define KS1H 4608
#define VS0H 9216
#define VS1H 13824
#define FA_SMEM_BYTES 45056

__global__ void __launch_bounds__(256, 2)
fused_attn(const __half* __restrict__ gQ, const __half* __restrict__ gK,
           const __half* __restrict__ gVt, const int* __restrict__ mask,
           float* __restrict__ attnOut, __half* __restrict__ gO)
{
    extern __shared__ char smc[];
    __half* smh = (__half*)smc;
    float*  Mf  = (float*)(smc + 36864);
    const uint32_t sb = smem_u32(smc);

    const int tid  = threadIdx.x;
    const int lane = tid & 31;
    const int warp = tid >> 5;
    const int g    = lane >> 2;
    const int t4   = lane & 3;
    const int l15  = lane & 15;
    const int lhi  = (lane >> 4) * 8;
    const int wrow = warp * 16;

    const int qb = blockIdx.x * QB;
    const int bh = blockIdx.y;
    const int zb = bh >> 4;
    const int zh = bh & 15;

    const __half* Q  = gQ + ((size_t)bh * SEQ + qb) * HDIM;
    const __half* K  = gK + (size_t)bh * SEQ * HDIM;
    const __half* Vt = gVt + (size_t)bh * HDIM * SEQ;
    float* attn = attnOut + ((size_t)(zh * BATCH + zb) * SEQ + qb) * SEQ;

    // mask -> additive float
    #pragma unroll
    for (int i = 0; i < SEQ / 256; ++i) {
        int c = i * 256 + tid;
        Mf[c] = mask[zb * SEQ + c] ? NEG_INF : 0.f;
    }
    // Q tile -> smem (overlay on KS/VS region)
    #pragma unroll
    for (int i = 0; i < 4; ++i) {
        int idx = i * 256 + tid;
        int r = idx >> 3, c = idx & 7;
        *(uint4*)(smh + r * FST + c * 8) = *(const uint4*)(Q + (size_t)r * HDIM + c * 8);
    }
    __syncthreads();

    // persistent Q A-fragments: 4 k16-steps x 4 regs
    uint32_t aq[4][4];
    #pragma unroll
    for (int ks = 0; ks < 4; ++ks)
        ldsm_x4(aq[ks], sb + ((wrow + l15) * FST + ks * 16 + lhi) * 2);
    __syncthreads();   // Qs dead before cp.async reuses region

    auto issueK = [&](int t, int buf) {
        const __half* Kt = K + (size_t)t * TC * HDIM;
        const uint32_t base = sb + (buf ? KS1H : KS0H) * 2;
        #pragma unroll
        for (int i = 0; i < 2; ++i) {
            int idx = i * 256 + tid;
            int r = idx >> 3, c = idx & 7;
            cp16(base + (r * FST + c * 8) * 2, Kt + r * HDIM + c * 8);
        }
    };
    auto issueV = [&](int t, int buf) {
        const __half* Vs = Vt + (size_t)t * TC;   // [dv][t] tile: row dv, cols t0..t0+63
        const uint32_t base = sb + (buf ? VS1H : VS0H) * 2;
        #pragma unroll
        for (int i = 0; i < 2; ++i) {
            int idx = i * 256 + tid;
            int r = idx >> 3, c = idx & 7;
            cp16(base + (r * FST + c * 8) * 2, Vs + (size_t)r * SEQ + c * 8);
        }
    };

    auto computeS = [&](float sacc[8][4], uint32_t ksb) {
        #pragma unroll
        for (int nt = 0; nt < 8; ++nt)
            #pragma unroll
            for (int e = 0; e < 4; ++e) sacc[nt][e] = 0.f;
        #pragma unroll
        for (int ks = 0; ks < 4; ++ks) {
            uint32_t bf[4][4];
            #pragma unroll
            for (int p = 0; p < 4; ++p)
                ldsm_x4(bf[p], ksb + ((p * 16 + l15) * FST + ks * 16 + lhi) * 2);
            #pragma unroll
            for (int p = 0; p < 4; ++p) {
                mma_f16(sacc[2 * p    ], aq[ks][0], aq[ks][1], aq[ks][2], aq[ks][3],
                        bf[p][0], bf[p][2]);
                mma_f16(sacc[2 * p + 1], aq[ks][0], aq[ks][1], aq[ks][2], aq[ks][3],
                        bf[p][1], bf[p][3]);
            }
        }
    };

    // ---------------- pass 1: online (m, l) ----------------
    float m0 = NEG_INF, m1 = NEG_INF, l0 = 0.f, l1 = 0.f;

    issueK(0, 0); cp_commit();
    for (int t = 0; t < SEQ / TC; ++t) {
        __syncthreads();
        if (t + 1 < SEQ / TC) issueK(t + 1, (t + 1) & 1);
        cp_commit();
        cp_wait1();
        __syncthreads();

        float sacc[8][4];
        computeS(sacc, sb + (((t & 1) ? KS1H : KS0H)) * 2);

        float tm0 = NEG_INF, tm1 = NEG_INF;
        #pragma unroll
        for (int nt = 0; nt < 8; ++nt) {
            float mk0 = Mf[t * TC + nt * 8 + t4 * 2];
            float mk1 = Mf[t * TC + nt * 8 + t4 * 2 + 1];
            sacc[nt][0] = sacc[nt][0] * SCALE2 + mk0;
            sacc[nt][1] = sacc[nt][1] * SCALE2 + mk1;
            sacc[nt][2] = sacc[nt][2] * SCALE2 + mk0;
            sacc[nt][3] = sacc[nt][3] * SCALE2 + mk1;
            tm0 = fmaxf(tm0, fmaxf(sacc[nt][0], sacc[nt][1]));
            tm1 = fmaxf(tm1, fmaxf(sacc[nt][2], sacc[nt][3]));
        }
        tm0 = fmaxf(tm0, __shfl_xor_sync(0xffffffffu, tm0, 1));
        tm0 = fmaxf(tm0, __shfl_xor_sync(0xffffffffu, tm0, 2));
        tm1 = fmaxf(tm1, __shfl_xor_sync(0xffffffffu, tm1, 1));
        tm1 = fmaxf(tm1, __shfl_xor_sync(0xffffffffu, tm1, 2));

        float mn0 = fmaxf(m0, tm0), mn1 = fmaxf(m1, tm1);
        float ms0 = (mn0 == NEG_INF) ? 0.f : mn0;
        float ms1 = (mn1 == NEG_INF) ? 0.f : mn1;

        float sum0 = 0.f, sum1 = 0.f;
        #pragma unroll
        for (int nt = 0; nt < 8; ++nt) {
            sum0 += ex2(sacc[nt][0] - ms0) + ex2(sacc[nt][1] - ms0);
            sum1 += ex2(sacc[nt][2] - ms1) + ex2(sacc[nt][3] - ms1);
        }
        sum0 += __shfl_xor_sync(0xffffffffu, sum0, 1);
        sum0 += __shfl_xor_sync(0xffffffffu, sum0, 2);
        sum1 += __shfl_xor_sync(0xffffffffu, sum1, 1);
        sum1 += __shfl_xor_sync(0xffffffffu, sum1, 2);

        float a0 = (m0 == NEG_INF) ? 0.f : ex2(m0 - ms0);
        float a1 = (m1 == NEG_INF) ? 0.f : ex2(m1 - ms1);
        l0 = l0 * a0 + sum0;
        l1 = l1 * a1 + sum1;
        m0 = mn0; m1 = mn1;
    }

    const float invl0 = (l0 > 0.f) ? 1.f / l0 : 0.f;
    const float invl1 = (l1 > 0.f) ? 1.f / l1 : 0.f;
    const float mf0 = (m0 == NEG_INF) ? 0.f : m0;
    const float mf1 = (m1 == NEG_INF) ? 0.f : m1;

    // ---------------- pass 2: recompute + P write + PV ----------------
    float oacc[8][4];
    #pragma unroll
    for (int nt = 0; nt < 8; ++nt)
        #pragma unroll
        for (int e = 0; e < 4; ++e) oacc[nt][e] = 0.f;

    issueK(0, 0); issueV(0, 0); cp_commit();
    for (int t = 0; t < SEQ / TC; ++t) {
        __syncthreads();
        if (t + 1 < SEQ / TC) { issueK(t + 1, (t + 1) & 1); issueV(t + 1, (t + 1) & 1); }
        cp_commit();
        cp_wait1();
        __syncthreads();

        float sacc[8][4];
        computeS(sacc, sb + (((t & 1) ? KS1H : KS0H)) * 2);
        const uint32_t vsb = sb + (((t & 1) ? VS1H : VS0H)) * 2;

        // normalize in place + direct attn write (float2, sector-aligned)
        #pragma unroll
        for (int nt = 0; nt < 8; ++nt) {
            float mk0 = Mf[t * TC + nt * 8 + t4 * 2];
            float mk1 = Mf[t * TC + nt * 8 + t4 * 2 + 1];
            sacc[nt][0] = ex2(sacc[nt][0] * SCALE2 + mk0 - mf0) * invl0;
            sacc[nt][1] = ex2(sacc[nt][1] * SCALE2 + mk1 - mf0) * invl0;
            sacc[nt][2] = ex2(sacc[nt][2] * SCALE2 + mk0 - mf1) * invl1;
            sacc[nt][3] = ex2(sacc[nt][3] * SCALE2 + mk1 - mf1) * invl1;
            float* d0 = attn + (size_t)(wrow + g) * SEQ + t * TC + nt * 8 + t4 * 2;
            *(float2*)d0 = make_float2(sacc[nt][0], sacc[nt][1]);
            *(float2*)(d0 + 8 * SEQ) = make_float2(sacc[nt][2], sacc[nt][3]);
        }

        // PV: A-frags straight from sacc (fp16 C-layout == A-layout)
        #pragma unroll
        for (int j = 0; j < 4; ++j) {
            uint32_t pa0 = f2h2(sacc[2 * j][0],     sacc[2 * j][1]);
            uint32_t pa1 = f2h2(sacc[2 * j][2],     sacc[2 * j][3]);
            uint32_t pa2 = f2h2(sacc[2 * j + 1][0], sacc[2 * j + 1][1]);
            uint32_t pa3 = f2h2(sacc[2 * j + 1][2], sacc[2 * j + 1][3]);
            uint32_t bf[4][4];
            #pragma unroll
            for (int p = 0; p < 4; ++p)
                ldsm_x4(bf[p], vsb + ((p * 16 + l15) * FST + j * 16 + lhi) * 2);
            #pragma unroll
            for (int p = 0; p < 4; ++p) {
                mma_f16(oacc[2 * p    ], pa0, pa1, pa2, pa3, bf[p][0], bf[p][2]);
                mma_f16(oacc[2 * p + 1], pa0, pa1, pa2, pa3, bf[p][1], bf[p][3]);
            }
        }
    }

    // write O block (fp16) to g_O [b*l][h*64+dv]
    #pragma unroll
    for (int nt = 0; nt < 8; ++nt) {
        int col = nt * 8 + t4 * 2;
        size_t r0 = ((size_t)zb * SEQ + qb + wrow + g) * DMODEL + zh * HDIM + col;
        *(uint32_t*)(gO + r0)               = f2h2(oacc[nt][0], oacc[nt][1]);
        *(uint32_t*)(gO + r0 + 8 * DMODEL)  = f2h2(oacc[nt][2], oacc[nt][3]);
    }
}

// ============================================================================
extern "C" void kernel_launch(void* const* d_in, const int* in_sizes, int n_in,
                              void* d_out, int out_size)
{
    const float* q    = (const float*)d_in[0];
    const float* k    = (const float*)d_in[1];
    const float* v    = (const float*)d_in[2];
    const int*   mask = (const int*)d_in[3];
    const float* Wq = (const float*)d_in[4];
    const float* bq = (const float*)d_in[5];
    const float* Wk = (const float*)d_in[6];
    const float* bk = (const float*)d_in[7];
    const float* Wv = (const float*)d_in[8];
    const float* bv = (const float*)d_in[9];
    const float* Wo = (const float*)d_in[10];
    const float* bo = (const float*)d_in[11];

    float* out  = (float*)d_out;                         // [4,2048,1024]
    float* attn = out + (size_t)TOK * DMODEL;            // [16,4,2048,2048]

    __half *gq, *gk, *gv, *go;
    cudaGetSymbolAddress((void**)&gq, g_Q);
    cudaGetSymbolAddress((void**)&gk, g_K);
    cudaGetSymbolAddress((void**)&gv, g_V);
    cudaGetSymbolAddress((void**)&go, g_O);

    static int attr_set = 0;
    if (!attr_set) {
        cudaFuncSetAttribute((const void*)proj_gemm<1,0>,
            cudaFuncAttributeMaxDynamicSharedMemorySize, PJ_SMEM_BYTES);
        cudaFuncSetAttribute((const void*)proj_gemm<0,1>,
            cudaFuncAttributeMaxDynamicSharedMemorySize, PJ_SMEM_BYTES);
        cudaFuncSetAttribute((const void*)fused_attn,
            cudaFuncAttributeMaxDynamicSharedMemorySize, FA_SMEM_BYTES);
        attr_set = 1;
    }

    dim3 blk(256);

    // merged Q/K/V projections (z selects input/weight/output; z==2 -> V^T)
    dim3 gqkv(DMODEL / 128, TOK / 128, 3);
    proj_gemm<1,0><<<gqkv, blk, PJ_SMEM_BYTES>>>(q, k, v, Wq, Wk, Wv,
                                                 bq, bk, bv, gq, gk, gv);

    // fused scores + softmax + attn-write + PV
    dim3 gfa(SEQ / QB, BATCH * HEADS);
    fused_attn<<<gfa, blk, FA_SMEM_BYTES>>>(gq, gk, gv, mask, attn, go);

    // output projection (fp16 A source, fp32 out)
    dim3 gout(DMODEL / 128, TOK / 128, 1);
    proj_gemm<0,1><<<gout, blk, PJ_SMEM_BYTES>>>(go, go, go, Wo, Wo, Wo,
                                                 bo, bo, bo, out, out, out);
}

// round 10
// speedup vs baseline: 2.1425x; 1.1138x over previous
#include <cuda_runtime.h>
#include <cuda_fp16.h>
#include <cstdint>

#define BATCH   4
#define HEADS   16
#define SEQ     2048
#define DMODEL  1024
#define HDIM    64
#define TOK     (BATCH*SEQ)       // 8192
// softmax in exp2 domain: scale = (1/sqrt(64)) * log2(e)
#define SCALE2  0.18033688011112042f

#define QB      128               // query rows per fused block
#define TC      64                // key tile

// -------- scratch (allocation-free rule: __device__ globals) --------
__device__ __half g_Q[BATCH*HEADS*SEQ*HDIM];   // [b][h][l][dh]
__device__ __half g_K[BATCH*HEADS*SEQ*HDIM];   // [b][h][t][dh]
__device__ __half g_V[BATCH*HEADS*SEQ*HDIM];   // [b][h][dh][t]  (transposed!)
__device__ __half g_O[TOK*DMODEL];             // [b*l][h*64+dv]
__device__ __half g_Xh[3*TOK*DMODEL];          // fp16 copies of q,k,v inputs
__device__ __half g_Wh[4*DMODEL*DMODEL];       // fp16 copies of Wq,Wk,Wv,Wo

__device__ __forceinline__ float ex2(float x) {
    float r;
    asm("ex2.approx.f32 %0, %1;" : "=f"(r) : "f"(x));
    return r;
}

__device__ __forceinline__ uint32_t f2h2(float lo, float hi) {
    __half2 h = __floats2half2_rn(lo, hi);
    return *reinterpret_cast<uint32_t*>(&h);
}

__device__ __forceinline__ void mma_f16(float c[4],
    uint32_t a0, uint32_t a1, uint32_t a2, uint32_t a3,
    uint32_t b0, uint32_t b1)
{
    asm volatile(
        "mma.sync.aligned.m16n8k16.row.col.f32.f16.f16.f32 "
        "{%0,%1,%2,%3}, {%4,%5,%6,%7}, {%8,%9}, {%0,%1,%2,%3};\n"
        : "+f"(c[0]), "+f"(c[1]), "+f"(c[2]), "+f"(c[3])
        : "r"(a0), "r"(a1), "r"(a2), "r"(a3), "r"(b0), "r"(b1));
}

__device__ __forceinline__ void ldsm_x4(uint32_t r[4], uint32_t addr) {
    asm volatile("ldmatrix.sync.aligned.m8n8.x4.shared.b16 {%0,%1,%2,%3}, [%4];"
        : "=r"(r[0]), "=r"(r[1]), "=r"(r[2]), "=r"(r[3]) : "r"(addr));
}
__device__ __forceinline__ void ldsm_x4_t(uint32_t r[4], uint32_t addr) {
    asm volatile("ldmatrix.sync.aligned.m8n8.x4.trans.shared.b16 {%0,%1,%2,%3}, [%4];"
        : "=r"(r[0]), "=r"(r[1]), "=r"(r[2]), "=r"(r[3]) : "r"(addr));
}

__device__ __forceinline__ uint32_t smem_u32(const void* p) {
    uint32_t a;
    asm("{ .reg .u64 t; cvta.to.shared.u64 t, %1; cvt.u32.u64 %0, t; }"
        : "=r"(a) : "l"(p));
    return a;
}
__device__ __forceinline__ void cp16(uint32_t dst, const void* src) {
    asm volatile("cp.async.cg.shared.global [%0], [%1], 16;" :: "r"(dst), "l"(src));
}
__device__ __forceinline__ void cp_commit() {
    asm volatile("cp.async.commit_group;" ::: "memory");
}
__device__ __forceinline__ void cp_wait1() {
    asm volatile("cp.async.wait_group 1;" ::: "memory");
}

#define NEG_INF __int_as_float(0xff800000)

// ============================================================================
// fp32 -> fp16 grid-stride converter (8 elements/thread)
// ============================================================================
__global__ void __launch_bounds__(256)
cvt_f2h(const float* __restrict__ src, __half* __restrict__ dst, int n8)
{
    int i = blockIdx.x * 256 + threadIdx.x;
    if (i < n8) {
        float4 a = ((const float4*)src)[i * 2];
        float4 b = ((const float4*)src)[i * 2 + 1];
        uint4 o;
        o.x = f2h2(a.x, a.y); o.y = f2h2(a.z, a.w);
        o.z = f2h2(b.x, b.y); o.w = f2h2(b.z, b.w);
        ((uint4*)dst)[i] = o;
    }
}

// ============================================================================
// fp16 projection GEMM: cp.async 2-stage double-buffered, ldmatrix frags.
// C[8192x1024] = A(fp16) @ W(fp16) + bias(fp32).
//  EPI 0: fp32 row-major out.
//  EPI 1: fp16 scatter. z<2 -> [b][h][l][dh]; z==2 -> V transposed [b][h][dh][t].
// smem halves: As0@0 [128][40] | As1@5120 | Bs0@10240 [32][136] | Bs1@14592
// total 18944 halves = 37888 B.
// ============================================================================
#define PAS 40
#define PBS 136
#define PJ_AS_H(buf) ((buf) ? 5120 : 0)
#define PJ_BS_H(buf) ((buf) ? 14592 : 10240)
#define PJ_SMEM_BYTES 37888

template<int EPI>
__global__ void __launch_bounds__(256, 2)
proj_gemm(const __half* __restrict__ A0, const __half* __restrict__ A1,
          const __half* __restrict__ A2,
          const __half* __restrict__ W0, const __half* __restrict__ W1,
          const __half* __restrict__ W2,
          const float* __restrict__ b0, const float* __restrict__ b1,
          const float* __restrict__ b2,
          void* o0v, void* o1v, void* o2v)
{
    extern __shared__ char smc[];
    const uint32_t sb = smem_u32(smc);

    const int z = blockIdx.z;
    const __half* Ag  = (z == 0) ? A0 : (z == 1) ? A1 : A2;
    const __half* Wg  = (z == 0) ? W0 : (z == 1) ? W1 : W2;
    const float* bias = (z == 0) ? b0 : (z == 1) ? b1 : b2;
    void* outv        = (z == 0) ? o0v : (z == 1) ? o1v : o2v;

    const int tid  = threadIdx.x;
    const int warp = tid >> 5;
    const int lane = tid & 31;
    const int wm   = warp & 3;          // 0..3 (M)
    const int wn   = warp >> 2;         // 0..1 (N)
    const int g    = lane >> 2;
    const int t4   = lane & 3;
    const int l15  = lane & 15;
    const int lhi  = (lane >> 4) * 8;

    const int bn = blockIdx.x * 128;
    const int bm = blockIdx.y * 128;

    float acc[2][8][4];
    #pragma unroll
    for (int mi = 0; mi < 2; ++mi)
        #pragma unroll
        for (int ni = 0; ni < 8; ++ni)
            #pragma unroll
            for (int e = 0; e < 4; ++e) acc[mi][ni][e] = 0.f;

    // cp.async stagers: A tile 128x32 halves, B tile 32x128 halves
    auto issue = [&](int t, int buf) {
        const int kg = t * 32;
        const uint32_t ab = sb + PJ_AS_H(buf) * 2;
        #pragma unroll
        for (int i = 0; i < 2; ++i) {
            int idx = i * 256 + tid;
            int r = idx >> 2, c = idx & 3;
            cp16(ab + (r * PAS + c * 8) * 2, Ag + (size_t)(bm + r) * DMODEL + kg + c * 8);
        }
        const uint32_t bb = sb + PJ_BS_H(buf) * 2;
        #pragma unroll
        for (int i = 0; i < 2; ++i) {
            int idx = i * 256 + tid;
            int r = idx >> 4, c = idx & 15;
            cp16(bb + (r * PBS + c * 8) * 2, Wg + (size_t)(kg + r) * DMODEL + bn + c * 8);
        }
    };

    auto compute = [&](int buf, int kk) {
        const uint32_t asb = sb + PJ_AS_H(buf) * 2;
        const uint32_t bsb = sb + PJ_BS_H(buf) * 2;
        uint32_t af[2][4];
        #pragma unroll
        for (int mi = 0; mi < 2; ++mi)
            ldsm_x4(af[mi], asb + ((wm * 32 + mi * 16 + l15) * PAS + kk + lhi) * 2);
        uint32_t bf[4][4];
        #pragma unroll
        for (int p = 0; p < 4; ++p)
            ldsm_x4_t(bf[p], bsb + ((kk + l15) * PBS + wn * 64 + p * 16 + lhi) * 2);
        #pragma unroll
        for (int mi = 0; mi < 2; ++mi)
            #pragma unroll
            for (int p = 0; p < 4; ++p) {
                mma_f16(acc[mi][2 * p    ], af[mi][0], af[mi][1], af[mi][2], af[mi][3],
                        bf[p][0], bf[p][1]);
                mma_f16(acc[mi][2 * p + 1], af[mi][0], af[mi][1], af[mi][2], af[mi][3],
                        bf[p][2], bf[p][3]);
            }
    };

    issue(0, 0); cp_commit();
    for (int t = 0; t < 32; ++t) {
        __syncthreads();                       // next buffer's readers done
        if (t + 1 < 32) issue(t + 1, (t + 1) & 1);
        cp_commit();
        cp_wait1();                            // tile t arrived
        __syncthreads();                       // publish arrivals
        compute(t & 1, 0);
        compute(t & 1, 16);
    }

    // ---- epilogue ----
    #pragma unroll
    for (int mi = 0; mi < 2; ++mi) {
        #pragma unroll
        for (int ni = 0; ni < 8; ++ni) {
            int row0 = bm + wm * 32 + mi * 16 + g;
            int col  = bn + wn * 64 + ni * 8 + t4 * 2;
            float v00 = acc[mi][ni][0] + bias[col];
            float v01 = acc[mi][ni][1] + bias[col + 1];
            float v10 = acc[mi][ni][2] + bias[col];
            float v11 = acc[mi][ni][3] + bias[col + 1];
            if (EPI == 0) {
                float* out = (float*)outv;
                *(float2*)(out + (size_t)row0 * DMODEL + col) = make_float2(v00, v01);
                *(float2*)(out + (size_t)(row0 + 8) * DMODEL + col) = make_float2(v10, v11);
            } else {
                __half* out = (__half*)outv;
                int h  = col >> 6;
                int dh = col & 63;
                if (z < 2) {
                    #pragma unroll
                    for (int rr = 0; rr < 2; ++rr) {
                        int row = row0 + rr * 8;
                        int b = row >> 11, l = row & (SEQ - 1);
                        uint32_t pv = rr ? f2h2(v10, v11) : f2h2(v00, v01);
                        *(uint32_t*)(out + (((size_t)(b * HEADS + h)) * SEQ + l) * HDIM + dh) = pv;
                    }
                } else {
                    // V transposed: [b][h][dh][t]
                    #pragma unroll
                    for (int rr = 0; rr < 2; ++rr) {
                        int row = row0 + rr * 8;
                        int b = row >> 11, l = row & (SEQ - 1);
                        float va = rr ? v10 : v00;
                        float vb = rr ? v11 : v01;
                        size_t base = ((size_t)(b * HEADS + h)) * HDIM;
                        out[(base + dh    ) * SEQ + l] = __float2half_rn(va);
                        out[(base + dh + 1) * SEQ + l] = __float2half_rn(vb);
                    }
                }
            }
        }
    }
}

// ============================================================================
// Fused attention fp16 (unchanged from R9): pass 1 = QK^T + online stats;
// pass 2 = recompute, normalize, fp32 attn write, PV with A-frags from sacc.
// smem halves: KS0@0 | KS1@4608 | VS0@9216 | VS1@13824  ([64][72] each)
// Mf fp32 @ byte 36864 (2048 floats). Qs[128][72] overlays KS/VS during init.
// ============================================================================
#define FST 72
#define KS0H 0
#define KS1H 4608
#define VS0H 9216
#define VS1H 13824
#define FA_SMEM_BYTES 45056

__global__ void __launch_bounds__(256, 2)
fused_attn(const __half* __restrict__ gQ, const __half* __restrict__ gK,
           const __half* __restrict__ gVt, const int* __restrict__ mask,
           float* __restrict__ attnOut, __half* __restrict__ gO)
{
    extern __shared__ char smc[];
    __half* smh = (__half*)smc;
    float*  Mf  = (float*)(smc + 36864);
    const uint32_t sb = smem_u32(smc);

    const int tid  = threadIdx.x;
    const int lane = tid & 31;
    const int warp = tid >> 5;
    const int g    = lane >> 2;
    const int t4   = lane & 3;
    const int l15  = lane & 15;
    const int lhi  = (lane >> 4) * 8;
    const int wrow = warp * 16;

    const int qb = blockIdx.x * QB;
    const int bh = blockIdx.y;
    const int zb = bh >> 4;
    const int zh = bh & 15;

    const __half* Q  = gQ + ((size_t)bh * SEQ + qb) * HDIM;
    const __half* K  = gK + (size_t)bh * SEQ * HDIM;
    const __half* Vt = gVt + (size_t)bh * HDIM * SEQ;
    float* attn = attnOut + ((size_t)(zh * BATCH + zb) * SEQ + qb) * SEQ;

    // mask -> additive float
    #pragma unroll
    for (int i = 0; i < SEQ / 256; ++i) {
        int c = i * 256 + tid;
        Mf[c] = mask[zb * SEQ + c] ? NEG_INF : 0.f;
    }
    // Q tile -> smem (overlay on KS/VS region)
    #pragma unroll
    for (int i = 0; i < 4; ++i) {
        int idx = i * 256 + tid;
        int r = idx >> 3, c = idx & 7;
        *(uint4*)(smh + r * FST + c * 8) = *(const uint4*)(Q + (size_t)r * HDIM + c * 8);
    }
    __syncthreads();

    // persistent Q A-fragments: 4 k16-steps x 4 regs
    uint32_t aq[4][4];
    #pragma unroll
    for (int ks = 0; ks < 4; ++ks)
        ldsm_x4(aq[ks], sb + ((wrow + l15) * FST + ks * 16 + lhi) * 2);
    __syncthreads();   // Qs dead before cp.async reuses region

    auto issueK = [&](int t, int buf) {
        const __half* Kt = K + (size_t)t * TC * HDIM;
        const uint32_t base = sb + (buf ? KS1H : KS0H) * 2;
        #pragma unroll
        for (int i = 0; i < 2; ++i) {
            int idx = i * 256 + tid;
            int r = idx >> 3, c = idx & 7;
            cp16(base + (r * FST + c * 8) * 2, Kt + r * HDIM + c * 8);
        }
    };
    auto issueV = [&](int t, int buf) {
        const __half* Vs = Vt + (size_t)t * TC;   // [dv][t] tile
        const uint32_t base = sb + (buf ? VS1H : VS0H) * 2;
        #pragma unroll
        for (int i = 0; i < 2; ++i) {
            int idx = i * 256 + tid;
            int r = idx >> 3, c = idx & 7;
            cp16(base + (r * FST + c * 8) * 2, Vs + (size_t)r * SEQ + c * 8);
        }
    };

    auto computeS = [&](float sacc[8][4], uint32_t ksb) {
        #pragma unroll
        for (int nt = 0; nt < 8; ++nt)
            #pragma unroll
            for (int e = 0; e < 4; ++e) sacc[nt][e] = 0.f;
        #pragma unroll
        for (int ks = 0; ks < 4; ++ks) {
            uint32_t bf[4][4];
            #pragma unroll
            for (int p = 0; p < 4; ++p)
                ldsm_x4(bf[p], ksb + ((p * 16 + l15) * FST + ks * 16 + lhi) * 2);
            #pragma unroll
            for (int p = 0; p < 4; ++p) {
                mma_f16(sacc[2 * p    ], aq[ks][0], aq[ks][1], aq[ks][2], aq[ks][3],
                        bf[p][0], bf[p][2]);
                mma_f16(sacc[2 * p + 1], aq[ks][0], aq[ks][1], aq[ks][2], aq[ks][3],
                        bf[p][1], bf[p][3]);
            }
        }
    };

    // ---------------- pass 1: online (m, l) ----------------
    float m0 = NEG_INF, m1 = NEG_INF, l0 = 0.f, l1 = 0.f;

    issueK(0, 0); cp_commit();
    for (int t = 0; t < SEQ / TC; ++t) {
        __syncthreads();
        if (t + 1 < SEQ / TC) issueK(t + 1, (t + 1) & 1);
        cp_commit();
        cp_wait1();
        __syncthreads();

        float sacc[8][4];
        computeS(sacc, sb + (((t & 1) ? KS1H : KS0H)) * 2);

        float tm0 = NEG_INF, tm1 = NEG_INF;
        #pragma unroll
        for (int nt = 0; nt < 8; ++nt) {
            float mk0 = Mf[t * TC + nt * 8 + t4 * 2];
            float mk1 = Mf[t * TC + nt * 8 + t4 * 2 + 1];
            sacc[nt][0] = sacc[nt][0] * SCALE2 + mk0;
            sacc[nt][1] = sacc[nt][1] * SCALE2 + mk1;
            sacc[nt][2] = sacc[nt][2] * SCALE2 + mk0;
            sacc[nt][3] = sacc[nt][3] * SCALE2 + mk1;
            tm0 = fmaxf(tm0, fmaxf(sacc[nt][0], sacc[nt][1]));
            tm1 = fmaxf(tm1, fmaxf(sacc[nt][2], sacc[nt][3]));
        }
        tm0 = fmaxf(tm0, __shfl_xor_sync(0xffffffffu, tm0, 1));
        tm0 = fmaxf(tm0, __shfl_xor_sync(0xffffffffu, tm0, 2));
        tm1 = fmaxf(tm1, __shfl_xor_sync(0xffffffffu, tm1, 1));
        tm1 = fmaxf(tm1, __shfl_xor_sync(0xffffffffu, tm1, 2));

        float mn0 = fmaxf(m0, tm0), mn1 = fmaxf(m1, tm1);
        float ms0 = (mn0 == NEG_INF) ? 0.f : mn0;
        float ms1 = (mn1 == NEG_INF) ? 0.f : mn1;

        float sum0 = 0.f, sum1 = 0.f;
        #pragma unroll
        for (int nt = 0; nt < 8; ++nt) {
            sum0 += ex2(sacc[nt][0] - ms0) + ex2(sacc[nt][1] - ms0);
            sum1 += ex2(sacc[nt][2] - ms1) + ex2(sacc[nt][3] - ms1);
        }
        sum0 += __shfl_xor_sync(0xffffffffu, sum0, 1);
        sum0 += __shfl_xor_sync(0xffffffffu, sum0, 2);
        sum1 += __shfl_xor_sync(0xffffffffu, sum1, 1);
        sum1 += __shfl_xor_sync(0xffffffffu, sum1, 2);

        float a0 = (m0 == NEG_INF) ? 0.f : ex2(m0 - ms0);
        float a1 = (m1 == NEG_INF) ? 0.f : ex2(m1 - ms1);
        l0 = l0 * a0 + sum0;
        l1 = l1 * a1 + sum1;
        m0 = mn0; m1 = mn1;
    }

    const float invl0 = (l0 > 0.f) ? 1.f / l0 : 0.f;
    const float invl1 = (l1 > 0.f) ? 1.f / l1 : 0.f;
    const float mf0 = (m0 == NEG_INF) ? 0.f : m0;
    const float mf1 = (m1 == NEG_INF) ? 0.f : m1;

    // ---------------- pass 2: recompute + P write + PV ----------------
    float oacc[8][4];
    #pragma unroll
    for (int nt = 0; nt < 8; ++nt)
        #pragma unroll
        for (int e = 0; e < 4; ++e) oacc[nt][e] = 0.f;

    issueK(0, 0); issueV(0, 0); cp_commit();
    for (int t = 0; t < SEQ / TC; ++t) {
        __syncthreads();
        if (t + 1 < SEQ / TC) { issueK(t + 1, (t + 1) & 1); issueV(t + 1, (t + 1) & 1); }
        cp_commit();
        cp_wait1();
        __syncthreads();

        float sacc[8][4];
        computeS(sacc, sb + (((t & 1) ? KS1H : KS0H)) * 2);
        const uint32_t vsb = sb + (((t & 1) ? VS1H : VS0H)) * 2;

        // normalize in place + direct attn write (float2, sector-aligned)
        #pragma unroll
        for (int nt = 0; nt < 8; ++nt) {
            float mk0 = Mf[t * TC + nt * 8 + t4 * 2];
            float mk1 = Mf[t * TC + nt * 8 + t4 * 2 + 1];
            sacc[nt][0] = ex2(sacc[nt][0] * SCALE2 + mk0 - mf0) * invl0;
            sacc[nt][1] = ex2(sacc[nt][1] * SCALE2 + mk1 - mf0) * invl0;
            sacc[nt][2] = ex2(sacc[nt][2] * SCALE2 + mk0 - mf1) * invl1;
            sacc[nt][3] = ex2(sacc[nt][3] * SCALE2 + mk1 - mf1) * invl1;
            float* d0 = attn + (size_t)(wrow + g) * SEQ + t * TC + nt * 8 + t4 * 2;
            *(float2*)d0 = make_float2(sacc[nt][0], sacc[nt][1]);
            *(float2*)(d0 + 8 * SEQ) = make_float2(sacc[nt][2], sacc[nt][3]);
        }

        // PV: A-frags straight from sacc (fp16 C-layout == A-layout)
        #pragma unroll
        for (int j = 0; j < 4; ++j) {
            uint32_t pa0 = f2h2(sacc[2 * j][0],     sacc[2 * j][1]);
            uint32_t pa1 = f2h2(sacc[2 * j][2],     sacc[2 * j][3]);
            uint32_t pa2 = f2h2(sacc[2 * j + 1][0], sacc[2 * j + 1][1]);
            uint32_t pa3 = f2h2(sacc[2 * j + 1][2], sacc[2 * j + 1][3]);
            uint32_t bf[4][4];
            #pragma unroll
            for (int p = 0; p < 4; ++p)
                ldsm_x4(bf[p], vsb + ((p * 16 + l15) * FST + j * 16 + lhi) * 2);
            #pragma unroll
            for (int p = 0; p < 4; ++p) {
                mma_f16(oacc[2 * p    ], pa0, pa1, pa2, pa3, bf[p][0], bf[p][2]);
                mma_f16(oacc[2 * p + 1], pa0, pa1, pa2, pa3, bf[p][1], bf[p][3]);
            }
        }
    }

    // write O block (fp16) to g_O [b*l][h*64+dv]
    #pragma unroll
    for (int nt = 0; nt < 8; ++nt) {
        int col = nt * 8 + t4 * 2;
        size_t r0 = ((size_t)zb * SEQ + qb + wrow + g) * DMODEL + zh * HDIM + col;
        *(uint32_t*)(gO + r0)               = f2h2(oacc[nt][0], oacc[nt][1]);
        *(uint32_t*)(gO + r0 + 8 * DMODEL)  = f2h2(oacc[nt][2], oacc[nt][3]);
    }
}

// ============================================================================
extern "C" void kernel_launch(void* const* d_in, const int* in_sizes, int n_in,
                              void* d_out, int out_size)
{
    const float* q    = (const float*)d_in[0];
    const float* k    = (const float*)d_in[1];
    const float* v    = (const float*)d_in[2];
    const int*   mask = (const int*)d_in[3];
    const float* Wq = (const float*)d_in[4];
    const float* bq = (const float*)d_in[5];
    const float* Wk = (const float*)d_in[6];
    const float* bk = (const float*)d_in[7];
    const float* Wv = (const float*)d_in[8];
    const float* bv = (const float*)d_in[9];
    const float* Wo = (const float*)d_in[10];
    const float* bo = (const float*)d_in[11];

    float* out  = (float*)d_out;                         // [4,2048,1024]
    float* attn = out + (size_t)TOK * DMODEL;            // [16,4,2048,2048]

    __half *gq, *gk, *gv, *go, *gx, *gw;
    cudaGetSymbolAddress((void**)&gq, g_Q);
    cudaGetSymbolAddress((void**)&gk, g_K);
    cudaGetSymbolAddress((void**)&gv, g_V);
    cudaGetSymbolAddress((void**)&go, g_O);
    cudaGetSymbolAddress((void**)&gx, g_Xh);
    cudaGetSymbolAddress((void**)&gw, g_Wh);

    static int attr_set = 0;
    if (!attr_set) {
        cudaFuncSetAttribute((const void*)proj_gemm<0>,
            cudaFuncAttributeMaxDynamicSharedMemorySize, PJ_SMEM_BYTES);
        cudaFuncSetAttribute((const void*)proj_gemm<1>,
            cudaFuncAttributeMaxDynamicSharedMemorySize, PJ_SMEM_BYTES);
        cudaFuncSetAttribute((const void*)fused_attn,
            cudaFuncAttributeMaxDynamicSharedMemorySize, FA_SMEM_BYTES);
        attr_set = 1;
    }

    dim3 blk(256);

    // fp32 -> fp16 pre-conversion (inputs + weights)
    const int NX8 = TOK * DMODEL / 8;          // 1M chunks per input
    const int NW8 = DMODEL * DMODEL / 8;       // 128K chunks per weight
    const size_t XN = (size_t)TOK * DMODEL;
    const size_t WN = (size_t)DMODEL * DMODEL;
    cvt_f2h<<<(NX8 + 255) / 256, blk>>>(q,  gx,          NX8);
    cvt_f2h<<<(NX8 + 255) / 256, blk>>>(k,  gx + XN,     NX8);
    cvt_f2h<<<(NX8 + 255) / 256, blk>>>(v,  gx + 2 * XN, NX8);
    cvt_f2h<<<(NW8 + 255) / 256, blk>>>(Wq, gw,          NW8);
    cvt_f2h<<<(NW8 + 255) / 256, blk>>>(Wk, gw + WN,     NW8);
    cvt_f2h<<<(NW8 + 255) / 256, blk>>>(Wv, gw + 2 * WN, NW8);
    cvt_f2h<<<(NW8 + 255) / 256, blk>>>(Wo, gw + 3 * WN, NW8);

    // merged Q/K/V projections (z selects input/weight/output; z==2 -> V^T)
    dim3 gqkv(DMODEL / 128, TOK / 128, 3);
    proj_gemm<1><<<gqkv, blk, PJ_SMEM_BYTES>>>(gx, gx + XN, gx + 2 * XN,
                                               gw, gw + WN, gw + 2 * WN,
                                               bq, bk, bv, gq, gk, gv);

    // fused scores + softmax + attn-write + PV
    dim3 gfa(SEQ / QB, BATCH * HEADS);
    fused_attn<<<gfa, blk, FA_SMEM_BYTES>>>(gq, gk, gv, mask, attn, go);

    // output projection (fp16 A = g_O, fp32 out)
    dim3 gout(DMODEL / 128, TOK / 128, 1);
    proj_gemm<0><<<gout, blk, PJ_SMEM_BYTES>>>(go, go, go,
                                               gw + 3 * WN, gw + 3 * WN, gw + 3 * WN,
                                               bo, bo, bo, out, out, out);
}

// round 11
// speedup vs baseline: 2.1998x; 1.0267x over previous
#include <cuda_runtime.h>
#include <cuda_fp16.h>
#include <cstdint>

#define BATCH   4
#define HEADS   16
#define SEQ     2048
#define DMODEL  1024
#define HDIM    64
#define TOK     (BATCH*SEQ)       // 8192
// softmax in exp2 domain: scale = (1/sqrt(64)) * log2(e)
#define SCALE2  0.18033688011112042f

#define QB      128               // query rows per fused block
#define TC      64                // key tile

// -------- scratch (allocation-free rule: __device__ globals) --------
__device__ __half g_Q[BATCH*HEADS*SEQ*HDIM];   // [b][h][l][dh]
__device__ __half g_K[BATCH*HEADS*SEQ*HDIM];   // [b][h][t][dh]
__device__ __half g_V[BATCH*HEADS*SEQ*HDIM];   // [b][h][dh][t]  (transposed!)
__device__ __half g_O[TOK*DMODEL];             // [b*l][h*64+dv]
__device__ __half g_Xh[3*TOK*DMODEL];          // fp16 copies of q,k,v inputs
__device__ __half g_Wh[4*DMODEL*DMODEL];       // fp16 copies of Wq,Wk,Wv,Wo

__device__ __forceinline__ float ex2(float x) {
    float r;
    asm("ex2.approx.f32 %0, %1;" : "=f"(r) : "f"(x));
    return r;
}

__device__ __forceinline__ uint32_t f2h2(float lo, float hi) {
    __half2 h = __floats2half2_rn(lo, hi);
    return *reinterpret_cast<uint32_t*>(&h);
}

__device__ __forceinline__ void mma_f16(float c[4],
    uint32_t a0, uint32_t a1, uint32_t a2, uint32_t a3,
    uint32_t b0, uint32_t b1)
{
    asm volatile(
        "mma.sync.aligned.m16n8k16.row.col.f32.f16.f16.f32 "
        "{%0,%1,%2,%3}, {%4,%5,%6,%7}, {%8,%9}, {%0,%1,%2,%3};\n"
        : "+f"(c[0]), "+f"(c[1]), "+f"(c[2]), "+f"(c[3])
        : "r"(a0), "r"(a1), "r"(a2), "r"(a3), "r"(b0), "r"(b1));
}

__device__ __forceinline__ void ldsm_x4(uint32_t r[4], uint32_t addr) {
    asm volatile("ldmatrix.sync.aligned.m8n8.x4.shared.b16 {%0,%1,%2,%3}, [%4];"
        : "=r"(r[0]), "=r"(r[1]), "=r"(r[2]), "=r"(r[3]) : "r"(addr));
}
__device__ __forceinline__ void ldsm_x4_t(uint32_t r[4], uint32_t addr) {
    asm volatile("ldmatrix.sync.aligned.m8n8.x4.trans.shared.b16 {%0,%1,%2,%3}, [%4];"
        : "=r"(r[0]), "=r"(r[1]), "=r"(r[2]), "=r"(r[3]) : "r"(addr));
}

__device__ __forceinline__ uint32_t smem_u32(const void* p) {
    uint32_t a;
    asm("{ .reg .u64 t; cvta.to.shared.u64 t, %1; cvt.u32.u64 %0, t; }"
        : "=r"(a) : "l"(p));
    return a;
}
__device__ __forceinline__ void cp16(uint32_t dst, const void* src) {
    asm volatile("cp.async.cg.shared.global [%0], [%1], 16;" :: "r"(dst), "l"(src));
}
__device__ __forceinline__ void cp_commit() {
    asm volatile("cp.async.commit_group;" ::: "memory");
}
__device__ __forceinline__ void cp_wait2() {
    asm volatile("cp.async.wait_group 2;" ::: "memory");
}

#define NEG_INF __int_as_float(0xff800000)

// ============================================================================
// fp32 -> fp16 converters, merged launches.
// cvt3: q,k,v -> g_Xh (each n8 chunks of 8).  cvt4: 4 weights -> g_Wh.
// ============================================================================
__device__ __forceinline__ void cvt_chunk(const float* __restrict__ src,
                                          __half* __restrict__ dst, int j)
{
    float4 a = ((const float4*)src)[j * 2];
    float4 b = ((const float4*)src)[j * 2 + 1];
    uint4 o;
    o.x = f2h2(a.x, a.y); o.y = f2h2(a.z, a.w);
    o.z = f2h2(b.x, b.y); o.w = f2h2(b.z, b.w);
    ((uint4*)dst)[j] = o;
}

__global__ void __launch_bounds__(256)
cvt3(const float* __restrict__ s0, const float* __restrict__ s1,
     const float* __restrict__ s2, __half* __restrict__ dst, int n8)
{
    int i = blockIdx.x * 256 + threadIdx.x;
    int which = i / n8, j = i - which * n8;
    const float* src = (which == 0) ? s0 : (which == 1) ? s1 : s2;
    cvt_chunk(src, dst + (size_t)which * n8 * 8, j);
}

__global__ void __launch_bounds__(256)
cvt4(const float* __restrict__ s0, const float* __restrict__ s1,
     const float* __restrict__ s2, const float* __restrict__ s3,
     __half* __restrict__ dst, int n8)
{
    int i = blockIdx.x * 256 + threadIdx.x;
    int which = i / n8, j = i - which * n8;
    const float* src = (which == 0) ? s0 : (which == 1) ? s1 :
                       (which == 2) ? s2 : s3;
    cvt_chunk(src, dst + (size_t)which * n8 * 8, j);
}

// ============================================================================
// fp16 projection GEMM: cp.async 3-stage pipelined, ldmatrix frags.
// C[8192x1024] = A(fp16) @ W(fp16) + bias(fp32).
//  EPI 0: fp32 row-major out.
//  EPI 1: fp16 scatter. z<2 -> [b][h][l][dh]; z==2 -> V transposed [b][h][dh][t].
// smem halves: As[3] 128x40 @ buf*5120 | Bs[3] 32x136 @ 15360+buf*4352
// total 28416 halves = 56832 B.
// ============================================================================
#define PAS 40
#define PBS 136
#define PJ_AS_H(buf) ((buf) * 5120)
#define PJ_BS_H(buf) (15360 + (buf) * 4352)
#define PJ_SMEM_BYTES 56832

template<int EPI>
__global__ void __launch_bounds__(256, 2)
proj_gemm(const __half* __restrict__ A0, const __half* __restrict__ A1,
          const __half* __restrict__ A2,
          const __half* __restrict__ W0, const __half* __restrict__ W1,
          const __half* __restrict__ W2,
          const float* __restrict__ b0, const float* __restrict__ b1,
          const float* __restrict__ b2,
          void* o0v, void* o1v, void* o2v)
{
    extern __shared__ char smc[];
    const uint32_t sb = smem_u32(smc);

    const int z = blockIdx.z;
    const __half* Ag  = (z == 0) ? A0 : (z == 1) ? A1 : A2;
    const __half* Wg  = (z == 0) ? W0 : (z == 1) ? W1 : W2;
    const float* bias = (z == 0) ? b0 : (z == 1) ? b1 : b2;
    void* outv        = (z == 0) ? o0v : (z == 1) ? o1v : o2v;

    const int tid  = threadIdx.x;
    const int warp = tid >> 5;
    const int lane = tid & 31;
    const int wm   = warp & 3;          // 0..3 (M)
    const int wn   = warp >> 2;         // 0..1 (N)
    const int g    = lane >> 2;
    const int t4   = lane & 3;
    const int l15  = lane & 15;
    const int lhi  = (lane >> 4) * 8;

    const int bn = blockIdx.x * 128;
    const int bm = blockIdx.y * 128;

    float acc[2][8][4];
    #pragma unroll
    for (int mi = 0; mi < 2; ++mi)
        #pragma unroll
        for (int ni = 0; ni < 8; ++ni)
            #pragma unroll
            for (int e = 0; e < 4; ++e) acc[mi][ni][e] = 0.f;

    auto issue = [&](int t, int buf) {
        const int kg = t * 32;
        const uint32_t ab = sb + PJ_AS_H(buf) * 2;
        #pragma unroll
        for (int i = 0; i < 2; ++i) {
            int idx = i * 256 + tid;
            int r = idx >> 2, c = idx & 3;
            cp16(ab + (r * PAS + c * 8) * 2, Ag + (size_t)(bm + r) * DMODEL + kg + c * 8);
        }
        const uint32_t bb = sb + PJ_BS_H(buf) * 2;
        #pragma unroll
        for (int i = 0; i < 2; ++i) {
            int idx = i * 256 + tid;
            int r = idx >> 4, c = idx & 15;
            cp16(bb + (r * PBS + c * 8) * 2, Wg + (size_t)(kg + r) * DMODEL + bn + c * 8);
        }
    };

    auto compute = [&](int buf, int kk) {
        const uint32_t asb = sb + PJ_AS_H(buf) * 2;
        const uint32_t bsb = sb + PJ_BS_H(buf) * 2;
        uint32_t af[2][4];
        #pragma unroll
        for (int mi = 0; mi < 2; ++mi)
            ldsm_x4(af[mi], asb + ((wm * 32 + mi * 16 + l15) * PAS + kk + lhi) * 2);
        uint32_t bf[4][4];
        #pragma unroll
        for (int p = 0; p < 4; ++p)
            ldsm_x4_t(bf[p], bsb + ((kk + l15) * PBS + wn * 64 + p * 16 + lhi) * 2);
        #pragma unroll
        for (int mi = 0; mi < 2; ++mi)
            #pragma unroll
            for (int p = 0; p < 4; ++p) {
                mma_f16(acc[mi][2 * p    ], af[mi][0], af[mi][1], af[mi][2], af[mi][3],
                        bf[p][0], bf[p][1]);
                mma_f16(acc[mi][2 * p + 1], af[mi][0], af[mi][1], af[mi][2], af[mi][3],
                        bf[p][2], bf[p][3]);
            }
    };

    issue(0, 0); cp_commit();
    issue(1, 1); cp_commit();
    for (int t = 0; t < 32; ++t) {
        __syncthreads();                       // tile t-1 readers done -> buf free
        if (t + 2 < 32) issue(t + 2, (t + 2) % 3);
        cp_commit();
        cp_wait2();                            // tile t arrived
        __syncthreads();                       // publish arrivals
        const int buf = t % 3;
        compute(buf, 0);
        compute(buf, 16);
    }

    // ---- epilogue ----
    #pragma unroll
    for (int mi = 0; mi < 2; ++mi) {
        #pragma unroll
        for (int ni = 0; ni < 8; ++ni) {
            int row0 = bm + wm * 32 + mi * 16 + g;
            int col  = bn + wn * 64 + ni * 8 + t4 * 2;
            float v00 = acc[mi][ni][0] + bias[col];
            float v01 = acc[mi][ni][1] + bias[col + 1];
            float v10 = acc[mi][ni][2] + bias[col];
            float v11 = acc[mi][ni][3] + bias[col + 1];
            if (EPI == 0) {
                float* out = (float*)outv;
                *(float2*)(out + (size_t)row0 * DMODEL + col) = make_float2(v00, v01);
                *(float2*)(out + (size_t)(row0 + 8) * DMODEL + col) = make_float2(v10, v11);
            } else {
                __half* out = (__half*)outv;
                int h  = col >> 6;
                int dh = col & 63;
                if (z < 2) {
                    #pragma unroll
                    for (int rr = 0; rr < 2; ++rr) {
                        int row = row0 + rr * 8;
                        int b = row >> 11, l = row & (SEQ - 1);
                        uint32_t pv = rr ? f2h2(v10, v11) : f2h2(v00, v01);
                        *(uint32_t*)(out + (((size_t)(b * HEADS + h)) * SEQ + l) * HDIM + dh) = pv;
                    }
                } else {
                    // V transposed: [b][h][dh][t]
                    #pragma unroll
                    for (int rr = 0; rr < 2; ++rr) {
                        int row = row0 + rr * 8;
                        int b = row >> 11, l = row & (SEQ - 1);
                        float va = rr ? v10 : v00;
                        float vb = rr ? v11 : v01;
                        size_t base = ((size_t)(b * HEADS + h)) * HDIM;
                        out[(base + dh    ) * SEQ + l] = __float2half_rn(va);
                        out[(base + dh + 1) * SEQ + l] = __float2half_rn(vb);
                    }
                }
            }
        }
    }
}

// ============================================================================
// Fused attention fp16, 3-stage cp.async: pass 1 = QK^T + online stats;
// pass 2 = recompute, normalize, streaming fp32 attn write, PV from sacc.
// smem halves: KS[3] @ buf*4608 | VS[3] @ 13824+buf*4608  ([64][72] each)
// Mf fp32 @ byte 55296 (2048 floats). Qs[128][72] overlays KS during init.
// total 63488 B.
// ============================================================================
#define FST 72
#define KS_H(buf) ((buf) * 4608)
#define VS_H(buf) (13824 + (buf) * 4608)
#define FA_SMEM_BYTES 63488

__global__ void __launch_bounds__(256, 2)
fused_attn(const __half* __restrict__ gQ, const __half* __restrict__ gK,
           const __half* __restrict__ gVt, const int* __restrict__ mask,
           float* __restrict__ attnOut, __half* __restrict__ gO)
{
    extern __shared__ char smc[];
    __half* smh = (__half*)smc;
    float*  Mf  = (float*)(smc + 55296);
    const uint32_t sb = smem_u32(smc);

    const int tid  = threadIdx.x;
    const int lane = tid & 31;
    const int warp = tid >> 5;
    const int g    = lane >> 2;
    const int t4   = lane & 3;
    const int l15  = lane & 15;
    const int lhi  = (lane >> 4) * 8;
    const int wrow = warp * 16;

    const int qb = blockIdx.x * QB;
    const int bh = blockIdx.y;
    const int zb = bh >> 4;
    const int zh = bh & 15;

    const __half* Q  = gQ + ((size_t)bh * SEQ + qb) * HDIM;
    const __half* K  = gK + (size_t)bh * SEQ * HDIM;
    const __half* Vt = gVt + (size_t)bh * HDIM * SEQ;
    float* attn = attnOut + ((size_t)(zh * BATCH + zb) * SEQ + qb) * SEQ;

    // mask -> additive float
    #pragma unroll
    for (int i = 0; i < SEQ / 256; ++i) {
        int c = i * 256 + tid;
        Mf[c] = mask[zb * SEQ + c] ? NEG_INF : 0.f;
    }
    // Q tile -> smem (overlay on KS region)
    #pragma unroll
    for (int i = 0; i < 4; ++i) {
        int idx = i * 256 + tid;
        int r = idx >> 3, c = idx & 7;
        *(uint4*)(smh + r * FST + c * 8) = *(const uint4*)(Q + (size_t)r * HDIM + c * 8);
    }
    __syncthreads();

    // persistent Q A-fragments: 4 k16-steps x 4 regs
    uint32_t aq[4][4];
    #pragma unroll
    for (int ks = 0; ks < 4; ++ks)
        ldsm_x4(aq[ks], sb + ((wrow + l15) * FST + ks * 16 + lhi) * 2);
    __syncthreads();   // Qs dead before cp.async reuses region

    auto issueK = [&](int t, int buf) {
        const __half* Kt = K + (size_t)t * TC * HDIM;
        const uint32_t base = sb + KS_H(buf) * 2;
        #pragma unroll
        for (int i = 0; i < 2; ++i) {
            int idx = i * 256 + tid;
            int r = idx >> 3, c = idx & 7;
            cp16(base + (r * FST + c * 8) * 2, Kt + r * HDIM + c * 8);
        }
    };
    auto issueV = [&](int t, int buf) {
        const __half* Vs = Vt + (size_t)t * TC;   // [dv][t] tile
        const uint32_t base = sb + VS_H(buf) * 2;
        #pragma unroll
        for (int i = 0; i < 2; ++i) {
            int idx = i * 256 + tid;
            int r = idx >> 3, c = idx & 7;
            cp16(base + (r * FST + c * 8) * 2, Vs + (size_t)r * SEQ + c * 8);
        }
    };

    auto computeS = [&](float sacc[8][4], uint32_t ksb) {
        #pragma unroll
        for (int nt = 0; nt < 8; ++nt)
            #pragma unroll
            for (int e = 0; e < 4; ++e) sacc[nt][e] = 0.f;
        #pragma unroll
        for (int ks = 0; ks < 4; ++ks) {
            uint32_t bf[4][4];
            #pragma unroll
            for (int p = 0; p < 4; ++p)
                ldsm_x4(bf[p], ksb + ((p * 16 + l15) * FST + ks * 16 + lhi) * 2);
            #pragma unroll
            for (int p = 0; p < 4; ++p) {
                mma_f16(sacc[2 * p    ], aq[ks][0], aq[ks][1], aq[ks][2], aq[ks][3],
                        bf[p][0], bf[p][2]);
                mma_f16(sacc[2 * p + 1], aq[ks][0], aq[ks][1], aq[ks][2], aq[ks][3],
                        bf[p][1], bf[p][3]);
            }
        }
    };

    // ---------------- pass 1: online (m, l) ----------------
    float m0 = NEG_INF, m1 = NEG_INF, l0 = 0.f, l1 = 0.f;

    issueK(0, 0); cp_commit();
    issueK(1, 1); cp_commit();
    for (int t = 0; t < SEQ / TC; ++t) {
        __syncthreads();
        if (t + 2 < SEQ / TC) issueK(t + 2, (t + 2) % 3);
        cp_commit();
        cp_wait2();
        __syncthreads();

        float sacc[8][4];
        computeS(sacc, sb + KS_H(t % 3) * 2);

        float tm0 = NEG_INF, tm1 = NEG_INF;
        #pragma unroll
        for (int nt = 0; nt < 8; ++nt) {
            float mk0 = Mf[t * TC + nt * 8 + t4 * 2];
            float mk1 = Mf[t * TC + nt * 8 + t4 * 2 + 1];
            sacc[nt][0] = sacc[nt][0] * SCALE2 + mk0;
            sacc[nt][1] = sacc[nt][1] * SCALE2 + mk1;
            sacc[nt][2] = sacc[nt][2] * SCALE2 + mk0;
            sacc[nt][3] = sacc[nt][3] * SCALE2 + mk1;
            tm0 = fmaxf(tm0, fmaxf(sacc[nt][0], sacc[nt][1]));
            tm1 = fmaxf(tm1, fmaxf(sacc[nt][2], sacc[nt][3]));
        }
        tm0 = fmaxf(tm0, __shfl_xor_sync(0xffffffffu, tm0, 1));
        tm0 = fmaxf(tm0, __shfl_xor_sync(0xffffffffu, tm0, 2));
        tm1 = fmaxf(tm1, __shfl_xor_sync(0xffffffffu, tm1, 1));
        tm1 = fmaxf(tm1, __shfl_xor_sync(0xffffffffu, tm1, 2));

        float mn0 = fmaxf(m0, tm0), mn1 = fmaxf(m1, tm1);
        float ms0 = (mn0 == NEG_INF) ? 0.f : mn0;
        float ms1 = (mn1 == NEG_INF) ? 0.f : mn1;

        float sum0 = 0.f, sum1 = 0.f;
        #pragma unroll
        for (int nt = 0; nt < 8; ++nt) {
            sum0 += ex2(sacc[nt][0] - ms0) + ex2(sacc[nt][1] - ms0);
            sum1 += ex2(sacc[nt][2] - ms1) + ex2(sacc[nt][3] - ms1);
        }
        sum0 += __shfl_xor_sync(0xffffffffu, sum0, 1);
        sum0 += __shfl_xor_sync(0xffffffffu, sum0, 2);
        sum1 += __shfl_xor_sync(0xffffffffu, sum1, 1);
        sum1 += __shfl_xor_sync(0xffffffffu, sum1, 2);

        float a0 = (m0 == NEG_INF) ? 0.f : ex2(m0 - ms0);
        float a1 = (m1 == NEG_INF) ? 0.f : ex2(m1 - ms1);
        l0 = l0 * a0 + sum0;
        l1 = l1 * a1 + sum1;
        m0 = mn0; m1 = mn1;
    }

    const float invl0 = (l0 > 0.f) ? 1.f / l0 : 0.f;
    const float invl1 = (l1 > 0.f) ? 1.f / l1 : 0.f;
    const float mf0 = (m0 == NEG_INF) ? 0.f : m0;
    const float mf1 = (m1 == NEG_INF) ? 0.f : m1;

    // ---------------- pass 2: recompute + P write + PV ----------------
    float oacc[8][4];
    #pragma unroll
    for (int nt = 0; nt < 8; ++nt)
        #pragma unroll
        for (int e = 0; e < 4; ++e) oacc[nt][e] = 0.f;

    __syncthreads();   // pass-1 compute fully done before re-staging buffers
    issueK(0, 0); issueV(0, 0); cp_commit();
    issueK(1, 1); issueV(1, 1); cp_commit();
    for (int t = 0; t < SEQ / TC; ++t) {
        __syncthreads();
        if (t + 2 < SEQ / TC) { issueK(t + 2, (t + 2) % 3); issueV(t + 2, (t + 2) % 3); }
        cp_commit();
        cp_wait2();
        __syncthreads();

        float sacc[8][4];
        computeS(sacc, sb + KS_H(t % 3) * 2);
        const uint32_t vsb = sb + VS_H(t % 3) * 2;

        // normalize in place + streaming attn write (float2, sector-aligned)
        #pragma unroll
        for (int nt = 0; nt < 8; ++nt) {
            float mk0 = Mf[t * TC + nt * 8 + t4 * 2];
            float mk1 = Mf[t * TC + nt * 8 + t4 * 2 + 1];
            sacc[nt][0] = ex2(sacc[nt][0] * SCALE2 + mk0 - mf0) * invl0;
            sacc[nt][1] = ex2(sacc[nt][1] * SCALE2 + mk1 - mf0) * invl0;
            sacc[nt][2] = ex2(sacc[nt][2] * SCALE2 + mk0 - mf1) * invl1;
            sacc[nt][3] = ex2(sacc[nt][3] * SCALE2 + mk1 - mf1) * invl1;
            float2* d0 = (float2*)(attn + (size_t)(wrow + g) * SEQ + t * TC + nt * 8 + t4 * 2);
            __stcs(d0, make_float2(sacc[nt][0], sacc[nt][1]));
            __stcs((float2*)((float*)d0 + 8 * SEQ), make_float2(sacc[nt][2], sacc[nt][3]));
        }

        // PV: A-frags straight from sacc (fp16 C-layout == A-layout)
        #pragma unroll
        for (int j = 0; j < 4; ++j) {
            uint32_t pa0 = f2h2(sacc[2 * j][0],     sacc[2 * j][1]);
            uint32_t pa1 = f2h2(sacc[2 * j][2],     sacc[2 * j][3]);
            uint32_t pa2 = f2h2(sacc[2 * j + 1][0], sacc[2 * j + 1][1]);
            uint32_t pa3 = f2h2(sacc[2 * j + 1][2], sacc[2 * j + 1][3]);
            uint32_t bf[4][4];
            #pragma unroll
            for (int p = 0; p < 4; ++p)
                ldsm_x4(bf[p], vsb + ((p * 16 + l15) * FST + j * 16 + lhi) * 2);
            #pragma unroll
            for (int p = 0; p < 4; ++p) {
                mma_f16(oacc[2 * p    ], pa0, pa1, pa2, pa3, bf[p][0], bf[p][2]);
                mma_f16(oacc[2 * p + 1], pa0, pa1, pa2, pa3, bf[p][1], bf[p][3]);
            }
        }
    }

    // write O block (fp16) to g_O [b*l][h*64+dv]
    #pragma unroll
    for (int nt = 0; nt < 8; ++nt) {
        int col = nt * 8 + t4 * 2;
        size_t r0 = ((size_t)zb * SEQ + qb + wrow + g) * DMODEL + zh * HDIM + col;
        *(uint32_t*)(gO + r0)               = f2h2(oacc[nt][0], oacc[nt][1]);
        *(uint32_t*)(gO + r0 + 8 * DMODEL)  = f2h2(oacc[nt][2], oacc[nt][3]);
    }
}

// ============================================================================
extern "C" void kernel_launch(void* const* d_in, const int* in_sizes, int n_in,
                              void* d_out, int out_size)
{
    const float* q    = (const float*)d_in[0];
    const float* k    = (const float*)d_in[1];
    const float* v    = (const float*)d_in[2];
    const int*   mask = (const int*)d_in[3];
    const float* Wq = (const float*)d_in[4];
    const float* bq = (const float*)d_in[5];
    const float* Wk = (const float*)d_in[6];
    const float* bk = (const float*)d_in[7];
    const float* Wv = (const float*)d_in[8];
    const float* bv = (const float*)d_in[9];
    const float* Wo = (const float*)d_in[10];
    const float* bo = (const float*)d_in[11];

    float* out  = (float*)d_out;                         // [4,2048,1024]
    float* attn = out + (size_t)TOK * DMODEL;            // [16,4,2048,2048]

    __half *gq, *gk, *gv, *go, *gx, *gw;
    cudaGetSymbolAddress((void**)&gq, g_Q);
    cudaGetSymbolAddress((void**)&gk, g_K);
    cudaGetSymbolAddress((void**)&gv, g_V);
    cudaGetSymbolAddress((void**)&go, g_O);
    cudaGetSymbolAddress((void**)&gx, g_Xh);
    cudaGetSymbolAddress((void**)&gw, g_Wh);

    static int attr_set = 0;
    if (!attr_set) {
        cudaFuncSetAttribute((const void*)proj_gemm<0>,
            cudaFuncAttributeMaxDynamicSharedMemorySize, PJ_SMEM_BYTES);
        cudaFuncSetAttribute((const void*)proj_gemm<1>,
            cudaFuncAttributeMaxDynamicSharedMemorySize, PJ_SMEM_BYTES);
        cudaFuncSetAttribute((const void*)fused_attn,
            cudaFuncAttributeMaxDynamicSharedMemorySize, FA_SMEM_BYTES);
        attr_set = 1;
    }

    dim3 blk(256);

    // fp32 -> fp16 pre-conversion (2 merged launches)
    const int NX8 = TOK * DMODEL / 8;          // 2^20 chunks per input
    const int NW8 = DMODEL * DMODEL / 8;       // 2^17 chunks per weight
    const size_t XN = (size_t)TOK * DMODEL;
    const size_t WN = (size_t)DMODEL * DMODEL;
    cvt3<<<(3 * NX8) / 256, blk>>>(q, k, v, gx, NX8);
    cvt4<<<(4 * NW8) / 256, blk>>>(Wq, Wk, Wv, Wo, gw, NW8);

    // merged Q/K/V projections (z selects input/weight/output; z==2 -> V^T)
    dim3 gqkv(DMODEL / 128, TOK / 128, 3);
    proj_gemm<1><<<gqkv, blk, PJ_SMEM_BYTES>>>(gx, gx + XN, gx + 2 * XN,
                                               gw, gw + WN, gw + 2 * WN,
                                               bq, bk, bv, gq, gk, gv);

    // fused scores + softmax + attn-write + PV
    dim3 gfa(SEQ / QB, BATCH * HEADS);
    fused_attn<<<gfa, blk, FA_SMEM_BYTES>>>(gq, gk, gv, mask, attn, go);

    // output projection (fp16 A = g_O, fp32 out)
    dim3 gout(DMODEL / 128, TOK / 128, 1);
    proj_gemm<0><<<gout, blk, PJ_SMEM_BYTES>>>(go, go, go,
                                               gw + 3 * WN, gw + 3 * WN, gw + 3 * WN,
                                               bo, bo, bo, out, out, out);
}

// round 12
// speedup vs baseline: 2.2547x; 1.0250x over previous
#include <cuda_runtime.h>
#include <cuda_fp16.h>
#include <cstdint>

#define BATCH   4
#define HEADS   16
#define SEQ     2048
#define DMODEL  1024
#define HDIM    64
#define TOK     (BATCH*SEQ)       // 8192
// softmax in exp2 domain: scale = (1/sqrt(64)) * log2(e)
#define SCALE2  0.18033688011112042f

#define QB      128               // query rows per fused block
#define TC      64                // key tile

// -------- scratch (allocation-free rule: __device__ globals) --------
__device__ __half g_Q[BATCH*HEADS*SEQ*HDIM];   // [b][h][l][dh]
__device__ __half g_K[BATCH*HEADS*SEQ*HDIM];   // [b][h][t][dh]
__device__ __half g_V[BATCH*HEADS*SEQ*HDIM];   // [b][h][dh][t]  (transposed!)
__device__ __half g_O[TOK*DMODEL];             // [b*l][h*64+dv]
__device__ __half g_Xh[3*TOK*DMODEL];          // fp16 copies of q,k,v inputs
__device__ __half g_Wh[4*DMODEL*DMODEL];       // fp16 copies of Wq,Wk,Wv,Wo

__device__ __forceinline__ float ex2(float x) {
    float r;
    asm("ex2.approx.f32 %0, %1;" : "=f"(r) : "f"(x));
    return r;
}
__device__ __forceinline__ float lg2(float x) {
    float r;
    asm("lg2.approx.f32 %0, %1;" : "=f"(r) : "f"(x));
    return r;
}

__device__ __forceinline__ uint32_t f2h2(float lo, float hi) {
    __half2 h = __floats2half2_rn(lo, hi);
    return *reinterpret_cast<uint32_t*>(&h);
}

__device__ __forceinline__ void mma_f16(float c[4],
    uint32_t a0, uint32_t a1, uint32_t a2, uint32_t a3,
    uint32_t b0, uint32_t b1)
{
    asm volatile(
        "mma.sync.aligned.m16n8k16.row.col.f32.f16.f16.f32 "
        "{%0,%1,%2,%3}, {%4,%5,%6,%7}, {%8,%9}, {%0,%1,%2,%3};\n"
        : "+f"(c[0]), "+f"(c[1]), "+f"(c[2]), "+f"(c[3])
        : "r"(a0), "r"(a1), "r"(a2), "r"(a3), "r"(b0), "r"(b1));
}

__device__ __forceinline__ void ldsm_x4(uint32_t r[4], uint32_t addr) {
    asm volatile("ldmatrix.sync.aligned.m8n8.x4.shared.b16 {%0,%1,%2,%3}, [%4];"
        : "=r"(r[0]), "=r"(r[1]), "=r"(r[2]), "=r"(r[3]) : "r"(addr));
}
__device__ __forceinline__ void ldsm_x4_t(uint32_t r[4], uint32_t addr) {
    asm volatile("ldmatrix.sync.aligned.m8n8.x4.trans.shared.b16 {%0,%1,%2,%3}, [%4];"
        : "=r"(r[0]), "=r"(r[1]), "=r"(r[2]), "=r"(r[3]) : "r"(addr));
}

__device__ __forceinline__ uint32_t smem_u32(const void* p) {
    uint32_t a;
    asm("{ .reg .u64 t; cvta.to.shared.u64 t, %1; cvt.u32.u64 %0, t; }"
        : "=r"(a) : "l"(p));
    return a;
}
__device__ __forceinline__ void cp16(uint32_t dst, const void* src) {
    asm volatile("cp.async.cg.shared.global [%0], [%1], 16;" :: "r"(dst), "l"(src));
}
__device__ __forceinline__ void cp_commit() {
    asm volatile("cp.async.commit_group;" ::: "memory");
}
__device__ __forceinline__ void cp_wait1() {
    asm volatile("cp.async.wait_group 1;" ::: "memory");
}

#define NEG_INF __int_as_float(0xff800000)

// ============================================================================
// fp32 -> fp16 converters, merged launches.
// ============================================================================
__device__ __forceinline__ void cvt_chunk(const float* __restrict__ src,
                                          __half* __restrict__ dst, int j)
{
    float4 a = ((const float4*)src)[j * 2];
    float4 b = ((const float4*)src)[j * 2 + 1];
    uint4 o;
    o.x = f2h2(a.x, a.y); o.y = f2h2(a.z, a.w);
    o.z = f2h2(b.x, b.y); o.w = f2h2(b.z, b.w);
    ((uint4*)dst)[j] = o;
}

__global__ void __launch_bounds__(256)
cvt3(const float* __restrict__ s0, const float* __restrict__ s1,
     const float* __restrict__ s2, __half* __restrict__ dst, int n8)
{
    int i = blockIdx.x * 256 + threadIdx.x;
    int which = i / n8, j = i - which * n8;
    const float* src = (which == 0) ? s0 : (which == 1) ? s1 : s2;
    cvt_chunk(src, dst + (size_t)which * n8 * 8, j);
}

__global__ void __launch_bounds__(256)
cvt4(const float* __restrict__ s0, const float* __restrict__ s1,
     const float* __restrict__ s2, const float* __restrict__ s3,
     __half* __restrict__ dst, int n8)
{
    int i = blockIdx.x * 256 + threadIdx.x;
    int which = i / n8, j = i - which * n8;
    const float* src = (which == 0) ? s0 : (which == 1) ? s1 :
                       (which == 2) ? s2 : s3;
    cvt_chunk(src, dst + (size_t)which * n8 * 8, j);
}

// ============================================================================
// fp16 projection GEMM: cp.async 3-stage, ONE sync/iter, ldmatrix frags.
// ============================================================================
#define PAS 40
#define PBS 136
#define PJ_AS_H(buf) ((buf) * 5120)
#define PJ_BS_H(buf) (15360 + (buf) * 4352)
#define PJ_SMEM_BYTES 56832

template<int EPI>
__global__ void __launch_bounds__(256, 2)
proj_gemm(const __half* __restrict__ A0, const __half* __restrict__ A1,
          const __half* __restrict__ A2,
          const __half* __restrict__ W0, const __half* __restrict__ W1,
          const __half* __restrict__ W2,
          const float* __restrict__ b0, const float* __restrict__ b1,
          const float* __restrict__ b2,
          void* o0v, void* o1v, void* o2v)
{
    extern __shared__ char smc[];
    const uint32_t sb = smem_u32(smc);

    const int z = blockIdx.z;
    const __half* Ag  = (z == 0) ? A0 : (z == 1) ? A1 : A2;
    const __half* Wg  = (z == 0) ? W0 : (z == 1) ? W1 : W2;
    const float* bias = (z == 0) ? b0 : (z == 1) ? b1 : b2;
    void* outv        = (z == 0) ? o0v : (z == 1) ? o1v : o2v;

    const int tid  = threadIdx.x;
    const int warp = tid >> 5;
    const int lane = tid & 31;
    const int wm   = warp & 3;
    const int wn   = warp >> 2;
    const int g    = lane >> 2;
    const int t4   = lane & 3;
    const int l15  = lane & 15;
    const int lhi  = (lane >> 4) * 8;

    const int bn = blockIdx.x * 128;
    const int bm = blockIdx.y * 128;

    float acc[2][8][4];
    #pragma unroll
    for (int mi = 0; mi < 2; ++mi)
        #pragma unroll
        for (int ni = 0; ni < 8; ++ni)
            #pragma unroll
            for (int e = 0; e < 4; ++e) acc[mi][ni][e] = 0.f;

    auto issue = [&](int t, int buf) {
        const int kg = t * 32;
        const uint32_t ab = sb + PJ_AS_H(buf) * 2;
        #pragma unroll
        for (int i = 0; i < 2; ++i) {
            int idx = i * 256 + tid;
            int r = idx >> 2, c = idx & 3;
            cp16(ab + (r * PAS + c * 8) * 2, Ag + (size_t)(bm + r) * DMODEL + kg + c * 8);
        }
        const uint32_t bb = sb + PJ_BS_H(buf) * 2;
        #pragma unroll
        for (int i = 0; i < 2; ++i) {
            int idx = i * 256 + tid;
            int r = idx >> 4, c = idx & 15;
            cp16(bb + (r * PBS + c * 8) * 2, Wg + (size_t)(kg + r) * DMODEL + bn + c * 8);
        }
    };

    auto compute = [&](int buf, int kk) {
        const uint32_t asb = sb + PJ_AS_H(buf) * 2;
        const uint32_t bsb = sb + PJ_BS_H(buf) * 2;
        uint32_t af[2][4];
        #pragma unroll
        for (int mi = 0; mi < 2; ++mi)
            ldsm_x4(af[mi], asb + ((wm * 32 + mi * 16 + l15) * PAS + kk + lhi) * 2);
        uint32_t bf[4][4];
        #pragma unroll
        for (int p = 0; p < 4; ++p)
            ldsm_x4_t(bf[p], bsb + ((kk + l15) * PBS + wn * 64 + p * 16 + lhi) * 2);
        #pragma unroll
        for (int mi = 0; mi < 2; ++mi)
            #pragma unroll
            for (int p = 0; p < 4; ++p) {
                mma_f16(acc[mi][2 * p    ], af[mi][0], af[mi][1], af[mi][2], af[mi][3],
                        bf[p][0], bf[p][1]);
                mma_f16(acc[mi][2 * p + 1], af[mi][0], af[mi][1], af[mi][2], af[mi][3],
                        bf[p][2], bf[p][3]);
            }
    };

    issue(0, 0); cp_commit();
    issue(1, 1); cp_commit();
    for (int t = 0; t < 32; ++t) {
        cp_wait1();                            // tile t arrived (all but newest group)
        __syncthreads();                       // visibility + buffer protection
        if (t + 2 < 32) issue(t + 2, (t + 2) % 3);
        cp_commit();                           // unconditional: 1 group/iter
        const int buf = t % 3;
        compute(buf, 0);
        compute(buf, 16);
    }

    // ---- epilogue ----
    #pragma unroll
    for (int mi = 0; mi < 2; ++mi) {
        #pragma unroll
        for (int ni = 0; ni < 8; ++ni) {
            int row0 = bm + wm * 32 + mi * 16 + g;
            int col  = bn + wn * 64 + ni * 8 + t4 * 2;
            float v00 = acc[mi][ni][0] + bias[col];
            float v01 = acc[mi][ni][1] + bias[col + 1];
            float v10 = acc[mi][ni][2] + bias[col];
            float v11 = acc[mi][ni][3] + bias[col + 1];
            if (EPI == 0) {
                float* out = (float*)outv;
                *(float2*)(out + (size_t)row0 * DMODEL + col) = make_float2(v00, v01);
                *(float2*)(out + (size_t)(row0 + 8) * DMODEL + col) = make_float2(v10, v11);
            } else {
                __half* out = (__half*)outv;
                int h  = col >> 6;
                int dh = col & 63;
                if (z < 2) {
                    #pragma unroll
                    for (int rr = 0; rr < 2; ++rr) {
                        int row = row0 + rr * 8;
                        int b = row >> 11, l = row & (SEQ - 1);
                        uint32_t pv = rr ? f2h2(v10, v11) : f2h2(v00, v01);
                        *(uint32_t*)(out + (((size_t)(b * HEADS + h)) * SEQ + l) * HDIM + dh) = pv;
                    }
                } else {
                    // V transposed: [b][h][dh][t]
                    #pragma unroll
                    for (int rr = 0; rr < 2; ++rr) {
                        int row = row0 + rr * 8;
                        int b = row >> 11, l = row & (SEQ - 1);
                        float va = rr ? v10 : v00;
                        float vb = rr ? v11 : v01;
                        size_t base = ((size_t)(b * HEADS + h)) * HDIM;
                        out[(base + dh    ) * SEQ + l] = __float2half_rn(va);
                        out[(base + dh + 1) * SEQ + l] = __float2half_rn(vb);
                    }
                }
            }
        }
    }
}

// ============================================================================
// Fused attention fp16, 3-stage cp.async, ONE sync/iter; pass 2 folds 1/l
// into the exponent (p = ex2(s*SCALE2 + mk - (m + log2 l))).
// smem halves: KS[3] @ buf*4608 | VS[3] @ 13824+buf*4608  ([64][72] each)
// Mf fp32 @ byte 55296 (2048 floats). Qs[128][72] overlays KS during init.
// ============================================================================
#define FST 72
#define KS_H(buf) ((buf) * 4608)
#define VS_H(buf) (13824 + (buf) * 4608)
#define FA_SMEM_BYTES 63488

__global__ void __launch_bounds__(256, 2)
fused_attn(const __half* __restrict__ gQ, const __half* __restrict__ gK,
           const __half* __restrict__ gVt, const int* __restrict__ mask,
           float* __restrict__ attnOut, __half* __restrict__ gO)
{
    extern __shared__ char smc[];
    __half* smh = (__half*)smc;
    float*  Mf  = (float*)(smc + 55296);
    const uint32_t sb = smem_u32(smc);

    const int tid  = threadIdx.x;
    const int lane = tid & 31;
    const int warp = tid >> 5;
    const int g    = lane >> 2;
    const int t4   = lane & 3;
    const int l15  = lane & 15;
    const int lhi  = (lane >> 4) * 8;
    const int wrow = warp * 16;

    const int qb = blockIdx.x * QB;
    const int bh = blockIdx.y;
    const int zb = bh >> 4;
    const int zh = bh & 15;

    const __half* Q  = gQ + ((size_t)bh * SEQ + qb) * HDIM;
    const __half* K  = gK + (size_t)bh * SEQ * HDIM;
    const __half* Vt = gVt + (size_t)bh * HDIM * SEQ;
    float* attn = attnOut + ((size_t)(zh * BATCH + zb) * SEQ + qb) * SEQ;

    // mask -> additive float
    #pragma unroll
    for (int i = 0; i < SEQ / 256; ++i) {
        int c = i * 256 + tid;
        Mf[c] = mask[zb * SEQ + c] ? NEG_INF : 0.f;
    }
    // Q tile -> smem (overlay on KS region)
    #pragma unroll
    for (int i = 0; i < 4; ++i) {
        int idx = i * 256 + tid;
        int r = idx >> 3, c = idx & 7;
        *(uint4*)(smh + r * FST + c * 8) = *(const uint4*)(Q + (size_t)r * HDIM + c * 8);
    }
    __syncthreads();

    // persistent Q A-fragments: 4 k16-steps x 4 regs
    uint32_t aq[4][4];
    #pragma unroll
    for (int ks = 0; ks < 4; ++ks)
        ldsm_x4(aq[ks], sb + ((wrow + l15) * FST + ks * 16 + lhi) * 2);
    __syncthreads();   // Qs dead before cp.async reuses region

    auto issueK = [&](int t, int buf) {
        const __half* Kt = K + (size_t)t * TC * HDIM;
        const uint32_t base = sb + KS_H(buf) * 2;
        #pragma unroll
        for (int i = 0; i < 2; ++i) {
            int idx = i * 256 + tid;
            int r = idx >> 3, c = idx & 7;
            cp16(base + (r * FST + c * 8) * 2, Kt + r * HDIM + c * 8);
        }
    };
    auto issueV = [&](int t, int buf) {
        const __half* Vs = Vt + (size_t)t * TC;   // [dv][t] tile
        const uint32_t base = sb + VS_H(buf) * 2;
        #pragma unroll
        for (int i = 0; i < 2; ++i) {
            int idx = i * 256 + tid;
            int r = idx >> 3, c = idx & 7;
            cp16(base + (r * FST + c * 8) * 2, Vs + (size_t)r * SEQ + c * 8);
        }
    };

    auto computeS = [&](float sacc[8][4], uint32_t ksb) {
        #pragma unroll
        for (int nt = 0; nt < 8; ++nt)
            #pragma unroll
            for (int e = 0; e < 4; ++e) sacc[nt][e] = 0.f;
        #pragma unroll
        for (int ks = 0; ks < 4; ++ks) {
            uint32_t bf[4][4];
            #pragma unroll
            for (int p = 0; p < 4; ++p)
                ldsm_x4(bf[p], ksb + ((p * 16 + l15) * FST + ks * 16 + lhi) * 2);
            #pragma unroll
            for (int p = 0; p < 4; ++p) {
                mma_f16(sacc[2 * p    ], aq[ks][0], aq[ks][1], aq[ks][2], aq[ks][3],
                        bf[p][0], bf[p][2]);
                mma_f16(sacc[2 * p + 1], aq[ks][0], aq[ks][1], aq[ks][2], aq[ks][3],
                        bf[p][1], bf[p][3]);
            }
        }
    };

    // ---------------- pass 1: online (m, l) ----------------
    float m0 = NEG_INF, m1 = NEG_INF, l0 = 0.f, l1 = 0.f;

    issueK(0, 0); cp_commit();
    issueK(1, 1); cp_commit();
    for (int t = 0; t < SEQ / TC; ++t) {
        cp_wait1();
        __syncthreads();
        if (t + 2 < SEQ / TC) issueK(t + 2, (t + 2) % 3);
        cp_commit();

        float sacc[8][4];
        computeS(sacc, sb + KS_H(t % 3) * 2);

        float tm0 = NEG_INF, tm1 = NEG_INF;
        #pragma unroll
        for (int nt = 0; nt < 8; ++nt) {
            float2 mk = *(const float2*)(Mf + t * TC + nt * 8 + t4 * 2);
            sacc[nt][0] = sacc[nt][0] * SCALE2 + mk.x;
            sacc[nt][1] = sacc[nt][1] * SCALE2 + mk.y;
            sacc[nt][2] = sacc[nt][2] * SCALE2 + mk.x;
            sacc[nt][3] = sacc[nt][3] * SCALE2 + mk.y;
            tm0 = fmaxf(tm0, fmaxf(sacc[nt][0], sacc[nt][1]));
            tm1 = fmaxf(tm1, fmaxf(sacc[nt][2], sacc[nt][3]));
        }
        tm0 = fmaxf(tm0, __shfl_xor_sync(0xffffffffu, tm0, 1));
        tm0 = fmaxf(tm0, __shfl_xor_sync(0xffffffffu, tm0, 2));
        tm1 = fmaxf(tm1, __shfl_xor_sync(0xffffffffu, tm1, 1));
        tm1 = fmaxf(tm1, __shfl_xor_sync(0xffffffffu, tm1, 2));

        float mn0 = fmaxf(m0, tm0), mn1 = fmaxf(m1, tm1);
        float ms0 = (mn0 == NEG_INF) ? 0.f : mn0;
        float ms1 = (mn1 == NEG_INF) ? 0.f : mn1;

        float sum0 = 0.f, sum1 = 0.f;
        #pragma unroll
        for (int nt = 0; nt < 8; ++nt) {
            sum0 += ex2(sacc[nt][0] - ms0) + ex2(sacc[nt][1] - ms0);
            sum1 += ex2(sacc[nt][2] - ms1) + ex2(sacc[nt][3] - ms1);
        }
        sum0 += __shfl_xor_sync(0xffffffffu, sum0, 1);
        sum0 += __shfl_xor_sync(0xffffffffu, sum0, 2);
        sum1 += __shfl_xor_sync(0xffffffffu, sum1, 1);
        sum1 += __shfl_xor_sync(0xffffffffu, sum1, 2);

        float a0 = (m0 == NEG_INF) ? 0.f : ex2(m0 - ms0);
        float a1 = (m1 == NEG_INF) ? 0.f : ex2(m1 - ms1);
        l0 = l0 * a0 + sum0;
        l1 = l1 * a1 + sum1;
        m0 = mn0; m1 = mn1;
    }

    // fold 1/l into exponent: c = m + log2(l)  (masked rows -> c = 0, s=-inf -> p=0)
    const float c0 = (l0 > 0.f) ? ((m0 == NEG_INF) ? 0.f : m0) + lg2(l0) : 0.f;
    const float c1 = (l1 > 0.f) ? ((m1 == NEG_INF) ? 0.f : m1) + lg2(l1) : 0.f;

    // ---------------- pass 2: recompute + P write + PV ----------------
    float oacc[8][4];
    #pragma unroll
    for (int nt = 0; nt < 8; ++nt)
        #pragma unroll
        for (int e = 0; e < 4; ++e) oacc[nt][e] = 0.f;

    __syncthreads();   // pass-1 compute fully done before re-staging buffers
    issueK(0, 0); issueV(0, 0); cp_commit();
    issueK(1, 1); issueV(1, 1); cp_commit();
    for (int t = 0; t < SEQ / TC; ++t) {
        cp_wait1();
        __syncthreads();
        if (t + 2 < SEQ / TC) { issueK(t + 2, (t + 2) % 3); issueV(t + 2, (t + 2) % 3); }
        cp_commit();

        float sacc[8][4];
        computeS(sacc, sb + KS_H(t % 3) * 2);
        const uint32_t vsb = sb + VS_H(t % 3) * 2;

        // normalize in place + streaming attn write (float2, sector-aligned)
        #pragma unroll
        for (int nt = 0; nt < 8; ++nt) {
            float2 mk = *(const float2*)(Mf + t * TC + nt * 8 + t4 * 2);
            float mk00 = mk.x - c0, mk01 = mk.y - c0;
            float mk10 = mk.x - c1, mk11 = mk.y - c1;
            sacc[nt][0] = ex2(sacc[nt][0] * SCALE2 + mk00);
            sacc[nt][1] = ex2(sacc[nt][1] * SCALE2 + mk01);
            sacc[nt][2] = ex2(sacc[nt][2] * SCALE2 + mk10);
            sacc[nt][3] = ex2(sacc[nt][3] * SCALE2 + mk11);
            float2* d0 = (float2*)(attn + (size_t)(wrow + g) * SEQ + t * TC + nt * 8 + t4 * 2);
            __stcs(d0, make_float2(sacc[nt][0], sacc[nt][1]));
            __stcs((float2*)((float*)d0 + 8 * SEQ), make_float2(sacc[nt][2], sacc[nt][3]));
        }

        // PV: A-frags straight from sacc (fp16 C-layout == A-layout)
        #pragma unroll
        for (int j = 0; j < 4; ++j) {
            uint32_t pa0 = f2h2(sacc[2 * j][0],     sacc[2 * j][1]);
            uint32_t pa1 = f2h2(sacc[2 * j][2],     sacc[2 * j][3]);
            uint32_t pa2 = f2h2(sacc[2 * j + 1][0], sacc[2 * j + 1][1]);
            uint32_t pa3 = f2h2(sacc[2 * j + 1][2], sacc[2 * j + 1][3]);
            uint32_t bf[4][4];
            #pragma unroll
            for (int p = 0; p < 4; ++p)
                ldsm_x4(bf[p], vsb + ((p * 16 + l15) * FST + j * 16 + lhi) * 2);
            #pragma unroll
            for (int p = 0; p < 4; ++p) {
                mma_f16(oacc[2 * p    ], pa0, pa1, pa2, pa3, bf[p][0], bf[p][2]);
                mma_f16(oacc[2 * p + 1], pa0, pa1, pa2, pa3, bf[p][1], bf[p][3]);
            }
        }
    }

    // write O block (fp16) to g_O [b*l][h*64+dv]
    #pragma unroll
    for (int nt = 0; nt < 8; ++nt) {
        int col = nt * 8 + t4 * 2;
        size_t r0 = ((size_t)zb * SEQ + qb + wrow + g) * DMODEL + zh * HDIM + col;
        *(uint32_t*)(gO + r0)               = f2h2(oacc[nt][0], oacc[nt][1]);
        *(uint32_t*)(gO + r0 + 8 * DMODEL)  = f2h2(oacc[nt][2], oacc[nt][3]);
    }
}

// ============================================================================
extern "C" void kernel_launch(void* const* d_in, const int* in_sizes, int n_in,
                              void* d_out, int out_size)
{
    const float* q    = (const float*)d_in[0];
    const float* k    = (const float*)d_in[1];
    const float* v    = (const float*)d_in[2];
    const int*   mask = (const int*)d_in[3];
    const float* Wq = (const float*)d_in[4];
    const float* bq = (const float*)d_in[5];
    const float* Wk = (const float*)d_in[6];
    const float* bk = (const float*)d_in[7];
    const float* Wv = (const float*)d_in[8];
    const float* bv = (const float*)d_in[9];
    const float* Wo = (const float*)d_in[10];
    const float* bo = (const float*)d_in[11];

    float* out  = (float*)d_out;                         // [4,2048,1024]
    float* attn = out + (size_t)TOK * DMODEL;            // [16,4,2048,2048]

    __half *gq, *gk, *gv, *go, *gx, *gw;
    cudaGetSymbolAddress((void**)&gq, g_Q);
    cudaGetSymbolAddress((void**)&gk, g_K);
    cudaGetSymbolAddress((void**)&gv, g_V);
    cudaGetSymbolAddress((void**)&go, g_O);
    cudaGetSymbolAddress((void**)&gx, g_Xh);
    cudaGetSymbolAddress((void**)&gw, g_Wh);

    static int attr_set = 0;
    if (!attr_set) {
        cudaFuncSetAttribute((const void*)proj_gemm<0>,
            cudaFuncAttributeMaxDynamicSharedMemorySize, PJ_SMEM_BYTES);
        cudaFuncSetAttribute((const void*)proj_gemm<1>,
            cudaFuncAttributeMaxDynamicSharedMemorySize, PJ_SMEM_BYTES);
        cudaFuncSetAttribute((const void*)fused_attn,
            cudaFuncAttributeMaxDynamicSharedMemorySize, FA_SMEM_BYTES);
        attr_set = 1;
    }

    dim3 blk(256);

    // fp32 -> fp16 pre-conversion (2 merged launches)
    const int NX8 = TOK * DMODEL / 8;
    const int NW8 = DMODEL * DMODEL / 8;
    const size_t XN = (size_t)TOK * DMODEL;
    const size_t WN = (size_t)DMODEL * DMODEL;
    cvt3<<<(3 * NX8) / 256, blk>>>(q, k, v, gx, NX8);
    cvt4<<<(4 * NW8) / 256, blk>>>(Wq, Wk, Wv, Wo, gw, NW8);

    // merged Q/K/V projections (z selects input/weight/output; z==2 -> V^T)
    dim3 gqkv(DMODEL / 128, TOK / 128, 3);
    proj_gemm<1><<<gqkv, blk, PJ_SMEM_BYTES>>>(gx, gx + XN, gx + 2 * XN,
                                               gw, gw + WN, gw + 2 * WN,
                                               bq, bk, bv, gq, gk, gv);

    // fused scores + softmax + attn-write + PV
    dim3 gfa(SEQ / QB, BATCH * HEADS);
    fused_attn<<<gfa, blk, FA_SMEM_BYTES>>>(gq, gk, gv, mask, attn, go);

    // output projection (fp16 A = g_O, fp32 out)
    dim3 gout(DMODEL / 128, TOK / 128, 1);
    proj_gemm<0><<<gout, blk, PJ_SMEM_BYTES>>>(go, go, go,
                                               gw + 3 * WN, gw + 3 * WN, gw + 3 * WN,
                                               bo, bo, bo, out, out, out);
}